// round 1
// baseline (speedup 1.0000x reference)
#include <cuda_runtime.h>
#include <math.h>

// Problem constants
#define B_   2
#define H_   16
#define T_   2048
#define D_   1024
#define HD_  64
#define M_   (B_*T_)      // 4096 rows
#define NQKV_ (3*D_)      // 3072

// Scratch (device globals: allocation-free rule)
__device__ float g_q[B_*H_*T_*HD_];    // [B,H,T,hd]
__device__ float g_k[B_*H_*T_*HD_];
__device__ float g_v[B_*H_*T_*HD_];
__device__ float g_att[B_*T_*D_];      // [B,T,H*hd]

// ---------------------------------------------------------------------------
// SGEMM: C[M,N] = A[M,K] @ B[K,N], 128x128x16 tile, 8x8 microtile, 256 thr.
// MODE 0: A = x, scatter epilogue into g_q/g_k/g_v ([B,H,T,hd] layout)
// MODE 1: A = g_att, plain store to Cout
// ---------------------------------------------------------------------------
template<int MODE>
__global__ __launch_bounds__(256, 2)
void sgemm_kernel(const float* __restrict__ Ain, const float* __restrict__ Bw,
                  float* __restrict__ Cout, int N, int K)
{
    constexpr int BM = 128, BN = 128, BK = 16;
    __shared__ float As[BK][BM];   // transposed A tile
    __shared__ float Bs[BK][BN];

    const float* A = (MODE == 0) ? Ain : g_att;

    const int tid = threadIdx.x;
    const int bm  = blockIdx.y;
    const int bn  = blockIdx.x;
    const int tr  = tid >> 4;      // 0..15
    const int tc  = tid & 15;      // 0..15

    float acc[8][8];
#pragma unroll
    for (int i = 0; i < 8; i++)
#pragma unroll
        for (int j = 0; j < 8; j++) acc[i][j] = 0.0f;

    const int rowA = tid >> 2;          // 0..63
    const int colA = (tid & 3) << 2;    // 0,4,8,12
    const int rowB = tid >> 5;          // 0..7
    const int colB = (tid & 31) << 2;   // 0..124

    const float* Ab = A + (size_t)bm * BM * K;
    const float* Bb = Bw + (size_t)bn * BN;

    for (int k0 = 0; k0 < K; k0 += BK) {
        float4 a0 = *(const float4*)(Ab + (size_t)rowA        * K + k0 + colA);
        float4 a1 = *(const float4*)(Ab + (size_t)(rowA + 64) * K + k0 + colA);
        float4 b0 = *(const float4*)(Bb + (size_t)(k0 + rowB)     * N + colB);
        float4 b1 = *(const float4*)(Bb + (size_t)(k0 + rowB + 8) * N + colB);

        As[colA + 0][rowA] = a0.x; As[colA + 1][rowA] = a0.y;
        As[colA + 2][rowA] = a0.z; As[colA + 3][rowA] = a0.w;
        As[colA + 0][rowA + 64] = a1.x; As[colA + 1][rowA + 64] = a1.y;
        As[colA + 2][rowA + 64] = a1.z; As[colA + 3][rowA + 64] = a1.w;
        *(float4*)&Bs[rowB][colB]     = b0;
        *(float4*)&Bs[rowB + 8][colB] = b1;
        __syncthreads();

#pragma unroll
        for (int k = 0; k < BK; k++) {
            float rm[8], rn[8];
            *(float4*)(rm)     = *(const float4*)&As[k][tr * 8];
            *(float4*)(rm + 4) = *(const float4*)&As[k][tr * 8 + 4];
            *(float4*)(rn)     = *(const float4*)&Bs[k][tc * 8];
            *(float4*)(rn + 4) = *(const float4*)&Bs[k][tc * 8 + 4];
#pragma unroll
            for (int i = 0; i < 8; i++)
#pragma unroll
                for (int j = 0; j < 8; j++)
                    acc[i][j] = fmaf(rm[i], rn[j], acc[i][j]);
        }
        __syncthreads();
    }

    // Epilogue
#pragma unroll
    for (int i = 0; i < 8; i++) {
        const int r = bm * BM + tr * 8 + i;     // global row (b*T + t)
#pragma unroll
        for (int j = 0; j < 8; j++) {
            const int c = bn * BN + tc * 8 + j; // global col
            if (MODE == 0) {
                const int b    = r >> 11;       // / T_
                const int t    = r & (T_ - 1);
                const int part = c >> 10;       // 0:q 1:k 2:v
                const int idx  = c & 1023;
                const int h    = idx >> 6;
                const int d    = idx & 63;
                float* dst = (part == 0) ? g_q : (part == 1) ? g_k : g_v;
                dst[(((size_t)b * H_ + h) * T_ + t) * HD_ + d] = acc[i][j];
            } else {
                Cout[(size_t)r * N + c] = acc[i][j];
            }
        }
    }
}

// ---------------------------------------------------------------------------
// RoPE (in-place on g_q, g_k). one thread per (b,h,t,j<32) pair.
// out[j] = a*cos - b*sin ; out[j+32] = b*cos + a*sin, angle = t * 10000^{-j/32}
// ---------------------------------------------------------------------------
__global__ void rope_kernel()
{
    const int idx = blockIdx.x * blockDim.x + threadIdx.x;  // B*H*T*32 threads
    const int j  = idx & 31;
    const int t  = (idx >> 5) & (T_ - 1);
    const int bh = idx >> 16;                                // 5 + 11 bits

    const float f   = exp2f(-(float)j * (13.287712379549449f / 32.0f)); // 10000^{-j/32}
    float s, c;
    sincosf((float)t * f, &s, &c);

    const size_t base = ((size_t)bh * T_ + t) * HD_;
    float a0 = g_q[base + j], b0 = g_q[base + j + 32];
    g_q[base + j]      = a0 * c - b0 * s;
    g_q[base + j + 32] = b0 * c + a0 * s;
    float a1 = g_k[base + j], b1 = g_k[base + j + 32];
    g_k[base + j]      = a1 * c - b1 * s;
    g_k[base + j + 32] = b1 * c + a1 * s;
}

// ---------------------------------------------------------------------------
// Flash attention, causal, fp32. Br=Bc=64, hd=64, 256 threads.
// Thread (tr,tc) owns rows {tr,tr+16,tr+32,tr+48} x cols/dims {tc,+16,+32,+48}
// (strided assignment -> conflict-free Ks reads at pitch 65).
// ---------------------------------------------------------------------------
#define FP_ 65                               // smem pitch
#define FLASH_SMEM (4 * 64 * FP_ * (int)sizeof(float))   // Qs,Ks,Vs,Ps = 66560B

__global__ __launch_bounds__(256)
void flash_kernel()
{
    extern __shared__ float sm[];
    float* Qs = sm;
    float* Ks = Qs + 64 * FP_;
    float* Vs = Ks + 64 * FP_;
    float* Ps = Vs + 64 * FP_;

    const int tid = threadIdx.x;
    const int tr  = tid >> 4;
    const int tc  = tid & 15;
    const int qtile = blockIdx.x;
    const int bh    = blockIdx.y;

    const float* Qg = g_q + ((size_t)bh * T_ + qtile * 64) * HD_;
    const float* Kg = g_k + (size_t)bh * T_ * HD_;
    const float* Vg = g_v + (size_t)bh * T_ * HD_;

    // load Q tile (64x64): 1024 float4 units
    for (int i = tid; i < 64 * 16; i += 256) {
        const int r  = i >> 4;
        const int c4 = (i & 15) << 2;
        float4 q4 = *(const float4*)(Qg + r * HD_ + c4);
        Qs[r * FP_ + c4 + 0] = q4.x; Qs[r * FP_ + c4 + 1] = q4.y;
        Qs[r * FP_ + c4 + 2] = q4.z; Qs[r * FP_ + c4 + 3] = q4.w;
    }

    float m_i[4], l_i[4], O[4][4];
#pragma unroll
    for (int i = 0; i < 4; i++) {
        m_i[i] = -INFINITY; l_i[i] = 0.0f;
#pragma unroll
        for (int j = 0; j < 4; j++) O[i][j] = 0.0f;
    }

    for (int kv = 0; kv <= qtile; kv++) {
        __syncthreads();   // prev iteration done with Ks/Vs
        const float* Kt = Kg + (size_t)kv * 64 * HD_;
        const float* Vt = Vg + (size_t)kv * 64 * HD_;
        for (int i = tid; i < 64 * 16; i += 256) {
            const int r  = i >> 4;
            const int c4 = (i & 15) << 2;
            float4 k4 = *(const float4*)(Kt + r * HD_ + c4);
            Ks[r * FP_ + c4 + 0] = k4.x; Ks[r * FP_ + c4 + 1] = k4.y;
            Ks[r * FP_ + c4 + 2] = k4.z; Ks[r * FP_ + c4 + 3] = k4.w;
            float4 v4 = *(const float4*)(Vt + r * HD_ + c4);
            Vs[r * FP_ + c4 + 0] = v4.x; Vs[r * FP_ + c4 + 1] = v4.y;
            Vs[r * FP_ + c4 + 2] = v4.z; Vs[r * FP_ + c4 + 3] = v4.w;
        }
        __syncthreads();

        // S = Q K^T (4x4 microtile)
        float s[4][4];
#pragma unroll
        for (int i = 0; i < 4; i++)
#pragma unroll
            for (int j = 0; j < 4; j++) s[i][j] = 0.0f;

#pragma unroll 8
        for (int k = 0; k < 64; k++) {
            float qv[4], kk[4];
#pragma unroll
            for (int i = 0; i < 4; i++) qv[i] = Qs[(tr + 16 * i) * FP_ + k];
#pragma unroll
            for (int j = 0; j < 4; j++) kk[j] = Ks[(tc + 16 * j) * FP_ + k];
#pragma unroll
            for (int i = 0; i < 4; i++)
#pragma unroll
                for (int j = 0; j < 4; j++)
                    s[i][j] = fmaf(qv[i], kk[j], s[i][j]);
        }

        const bool diag = (kv == qtile);
#pragma unroll
        for (int i = 0; i < 4; i++)
#pragma unroll
            for (int j = 0; j < 4; j++) {
                s[i][j] *= 0.125f;   // 1/sqrt(64)
                if (diag && (tc + 16 * j) > (tr + 16 * i)) s[i][j] = -1e30f;
            }

        // Online softmax, rowwise (16 lanes per row)
#pragma unroll
        for (int i = 0; i < 4; i++) {
            float rm = fmaxf(fmaxf(s[i][0], s[i][1]), fmaxf(s[i][2], s[i][3]));
#pragma unroll
            for (int off = 8; off > 0; off >>= 1)
                rm = fmaxf(rm, __shfl_xor_sync(0xffffffffu, rm, off, 16));
            const float mnew  = fmaxf(m_i[i], rm);
            const float alpha = __expf(m_i[i] - mnew);
            m_i[i] = mnew;
            float rs = 0.0f;
#pragma unroll
            for (int j = 0; j < 4; j++) {
                const float p = __expf(s[i][j] - mnew);
                s[i][j] = p;
                rs += p;
            }
#pragma unroll
            for (int off = 8; off > 0; off >>= 1)
                rs += __shfl_xor_sync(0xffffffffu, rs, off, 16);
            l_i[i] = l_i[i] * alpha + rs;
#pragma unroll
            for (int j = 0; j < 4; j++) {
                O[i][j] *= alpha;
                Ps[(tr + 16 * i) * FP_ + (tc + 16 * j)] = s[i][j];
            }
        }
        __syncthreads();

        // O += P @ V
#pragma unroll 8
        for (int c = 0; c < 64; c++) {
            float pv[4], vv[4];
#pragma unroll
            for (int i = 0; i < 4; i++) pv[i] = Ps[(tr + 16 * i) * FP_ + c];
#pragma unroll
            for (int j = 0; j < 4; j++) vv[j] = Vs[c * FP_ + tc + 16 * j];
#pragma unroll
            for (int i = 0; i < 4; i++)
#pragma unroll
                for (int j = 0; j < 4; j++)
                    O[i][j] = fmaf(pv[i], vv[j], O[i][j]);
        }
    }

    // epilogue: att[b, t, h*64+d]
    const int b = bh >> 4;
    const int h = bh & 15;
#pragma unroll
    for (int i = 0; i < 4; i++) {
        const int trow = qtile * 64 + tr + 16 * i;
        const float inv_l = 1.0f / l_i[i];
#pragma unroll
        for (int j = 0; j < 4; j++) {
            g_att[(((size_t)b * T_ + trow) * H_ + h) * HD_ + tc + 16 * j] = O[i][j] * inv_l;
        }
    }
}

// ---------------------------------------------------------------------------
extern "C" void kernel_launch(void* const* d_in, const int* in_sizes, int n_in,
                              void* d_out, int out_size)
{
    const float* x     = (const float*)d_in[0];
    // d_in[1] = mask (causal, known statically — ignored)
    const float* w_qkv = (const float*)d_in[2];
    const float* w_out = (const float*)d_in[3];
    float* out = (float*)d_out;

    cudaFuncSetAttribute(flash_kernel,
                         cudaFuncAttributeMaxDynamicSharedMemorySize, FLASH_SMEM);

    // 1) qkv = x @ w_qkv  -> scatter to g_q/g_k/g_v
    dim3 g1(NQKV_ / 128, M_ / 128);
    sgemm_kernel<0><<<g1, 256>>>(x, w_qkv, nullptr, NQKV_, D_);

    // 2) RoPE on q, k
    rope_kernel<<<(B_ * H_ * T_ * 32) / 256, 256>>>();

    // 3) causal flash attention -> g_att
    flash_kernel<<<dim3(T_ / 64, B_ * H_), 256, FLASH_SMEM>>>();

    // 4) out = att @ w_out
    dim3 g2(D_ / 128, M_ / 128);
    sgemm_kernel<1><<<g2, 256>>>(nullptr, w_out, out, D_, D_);
}

// round 5
// speedup vs baseline: 1.0712x; 1.0712x over previous
#include <cuda_runtime.h>
#include <math.h>
#include <stdint.h>

// Problem constants
#define B_   2
#define H_   16
#define T_   2048
#define D_   1024
#define HD_  64
#define M_   (B_*T_)      // 4096 rows
#define NQKV_ (3*D_)      // 3072

// Scratch (device globals: allocation-free rule)
__device__ float g_q[B_*H_*T_*HD_];    // [B,H,T,hd]
__device__ float g_k[B_*H_*T_*HD_];
__device__ float g_v[B_*H_*T_*HD_];
__device__ float g_att[B_*T_*D_];      // [B,T,H*hd]

__device__ __forceinline__ uint32_t smem_u32(const void* p) {
    uint32_t a;
    asm("{ .reg .u64 t; cvta.to.shared.u64 t, %1; cvt.u32.u64 %0, t; }" : "=r"(a) : "l"(p));
    return a;
}
__device__ __forceinline__ void cp_async16(uint32_t dst, const void* src) {
    asm volatile("cp.async.cg.shared.global [%0], [%1], 16;" :: "r"(dst), "l"(src));
}
__device__ __forceinline__ void cp_commit() { asm volatile("cp.async.commit_group;" ::: "memory"); }
__device__ __forceinline__ void cp_wait0()  { asm volatile("cp.async.wait_group 0;" ::: "memory"); }

// ---------------------------------------------------------------------------
// SGEMM: C[M,N] = A[M,K] @ B[K,N], 128x128x16 tile, 8x8 microtile, 256 thr.
// Double-buffered: B tiles via cp.async, A tiles via register staging.
// MODE 0: A = x, scatter epilogue into g_q/g_k/g_v ([B,H,T,hd] layout)
// MODE 1: A = g_att, plain store to Cout
// ---------------------------------------------------------------------------
template<int MODE>
__global__ __launch_bounds__(256, 2)
void sgemm_kernel(const float* __restrict__ Ain, const float* __restrict__ Bw,
                  float* __restrict__ Cout, int N, int K)
{
    constexpr int BM = 128, BN = 128, BK = 16;
    __shared__ float As[2][BK][BM];   // transposed A tile
    __shared__ float Bs[2][BK][BN];

    const float* A = (MODE == 0) ? Ain : g_att;

    const int tid = threadIdx.x;
    const int bm  = blockIdx.y;
    const int bn  = blockIdx.x;
    const int tr  = tid >> 4;      // 0..15
    const int tc  = tid & 15;      // 0..15

    float acc[8][8];
#pragma unroll
    for (int i = 0; i < 8; i++)
#pragma unroll
        for (int j = 0; j < 8; j++) acc[i][j] = 0.0f;

    const int rowA = tid >> 2;          // 0..63
    const int colA = (tid & 3) << 2;    // 0,4,8,12
    const int rowB = tid >> 5;          // 0..7
    const int colB = (tid & 31) << 2;   // 0..124

    const float* Ab = A + (size_t)bm * BM * K;
    const float* Bb = Bw + (size_t)bn * BN;

    const uint32_t bs_base = smem_u32(&Bs[0][0][0]);
    const uint32_t bs_off0 = (uint32_t)((rowB * BN + colB) * 4);
    const uint32_t bs_off1 = (uint32_t)(((rowB + 8) * BN + colB) * 4);
    const uint32_t bs_buf  = (uint32_t)(BK * BN * 4);

    const int NT = K / BK;

    // prologue: tile 0
    {
        float4 a0 = *(const float4*)(Ab + (size_t)rowA        * K + colA);
        float4 a1 = *(const float4*)(Ab + (size_t)(rowA + 64) * K + colA);
        cp_async16(bs_base + bs_off0, Bb + (size_t)rowB       * N + colB);
        cp_async16(bs_base + bs_off1, Bb + (size_t)(rowB + 8) * N + colB);
        cp_commit();
        As[0][colA + 0][rowA] = a0.x; As[0][colA + 1][rowA] = a0.y;
        As[0][colA + 2][rowA] = a0.z; As[0][colA + 3][rowA] = a0.w;
        As[0][colA + 0][rowA + 64] = a1.x; As[0][colA + 1][rowA + 64] = a1.y;
        As[0][colA + 2][rowA + 64] = a1.z; As[0][colA + 3][rowA + 64] = a1.w;
        cp_wait0();
        __syncthreads();
    }

    for (int t = 0; t < NT; t++) {
        const int buf = t & 1;

        float4 n0, n1;
        if (t + 1 < NT) {
            const int k0 = (t + 1) * BK;
            n0 = *(const float4*)(Ab + (size_t)rowA        * K + k0 + colA);
            n1 = *(const float4*)(Ab + (size_t)(rowA + 64) * K + k0 + colA);
            const uint32_t bdst = bs_base + (buf ^ 1) * bs_buf;
            cp_async16(bdst + bs_off0, Bb + (size_t)(k0 + rowB)     * N + colB);
            cp_async16(bdst + bs_off1, Bb + (size_t)(k0 + rowB + 8) * N + colB);
            cp_commit();
        }

#pragma unroll
        for (int k = 0; k < BK; k++) {
            float rm[8], rn[8];
            *(float4*)(rm)     = *(const float4*)&As[buf][k][tr * 8];
            *(float4*)(rm + 4) = *(const float4*)&As[buf][k][tr * 8 + 4];
            *(float4*)(rn)     = *(const float4*)&Bs[buf][k][tc * 8];
            *(float4*)(rn + 4) = *(const float4*)&Bs[buf][k][tc * 8 + 4];
#pragma unroll
            for (int i = 0; i < 8; i++)
#pragma unroll
                for (int j = 0; j < 8; j++)
                    acc[i][j] = fmaf(rm[i], rn[j], acc[i][j]);
        }

        if (t + 1 < NT) {
            const int nb = buf ^ 1;
            As[nb][colA + 0][rowA] = n0.x; As[nb][colA + 1][rowA] = n0.y;
            As[nb][colA + 2][rowA] = n0.z; As[nb][colA + 3][rowA] = n0.w;
            As[nb][colA + 0][rowA + 64] = n1.x; As[nb][colA + 1][rowA + 64] = n1.y;
            As[nb][colA + 2][rowA + 64] = n1.z; As[nb][colA + 3][rowA + 64] = n1.w;
            cp_wait0();
            __syncthreads();
        }
    }

    // Epilogue (identical to R1)
#pragma unroll
    for (int i = 0; i < 8; i++) {
        const int r = bm * BM + tr * 8 + i;     // global row (b*T + t)
#pragma unroll
        for (int j = 0; j < 8; j++) {
            const int c = bn * BN + tc * 8 + j; // global col
            if (MODE == 0) {
                const int b    = r >> 11;       // / T_
                const int t    = r & (T_ - 1);
                const int part = c >> 10;       // 0:q 1:k 2:v
                const int idx  = c & 1023;
                const int h    = idx >> 6;
                const int d    = idx & 63;
                float* dst = (part == 0) ? g_q : (part == 1) ? g_k : g_v;
                dst[(((size_t)b * H_ + h) * T_ + t) * HD_ + d] = acc[i][j];
            } else {
                Cout[(size_t)r * N + c] = acc[i][j];
            }
        }
    }
}

// ---------------------------------------------------------------------------
// RoPE (in-place on g_q, g_k). one thread per (b,h,t,j<32) pair.
// ---------------------------------------------------------------------------
__global__ void rope_kernel()
{
    const int idx = blockIdx.x * blockDim.x + threadIdx.x;  // B*H*T*32 threads
    const int j  = idx & 31;
    const int t  = (idx >> 5) & (T_ - 1);
    const int bh = idx >> 16;                                // 5 + 11 bits

    const float f   = exp2f(-(float)j * (13.287712379549449f / 32.0f)); // 10000^{-j/32}
    float s, c;
    sincosf((float)t * f, &s, &c);

    const size_t base = ((size_t)bh * T_ + t) * HD_;
    float a0 = g_q[base + j], b0 = g_q[base + j + 32];
    g_q[base + j]      = a0 * c - b0 * s;
    g_q[base + j + 32] = b0 * c + a0 * s;
    float a1 = g_k[base + j], b1 = g_k[base + j + 32];
    g_k[base + j]      = a1 * c - b1 * s;
    g_k[base + j + 32] = b1 * c + a1 * s;
}

// ---------------------------------------------------------------------------
// Flash attention, causal, fp32. Br=Bc=64, 256 threads. K/V double-buffered
// via register staging (LDG issued at tile start, stored after PV compute).
// ---------------------------------------------------------------------------
#define FP_ 65                                 // smem pitch
#define FTILE_ (64 * FP_)
#define FLASH_SMEM (6 * FTILE_ * (int)sizeof(float))   // Qs + Ks[2] + Vs[2] + Ps

__global__ __launch_bounds__(256, 2)
void flash_kernel()
{
    extern __shared__ float sm[];
    float* Qs = sm;                    // [64][65]
    float* Ks0 = Qs + FTILE_;
    float* Ks1 = Ks0 + FTILE_;
    float* Vs0 = Ks1 + FTILE_;
    float* Vs1 = Vs0 + FTILE_;
    float* Ps  = Vs1 + FTILE_;

    const int tid = threadIdx.x;
    const int tr  = tid >> 4;
    const int tc  = tid & 15;
    const int qtile = blockIdx.x;
    const int bh    = blockIdx.y;

    const float* Qg = g_q + ((size_t)bh * T_ + qtile * 64) * HD_;
    const float* Kg = g_k + (size_t)bh * T_ * HD_;
    const float* Vg = g_v + (size_t)bh * T_ * HD_;

    const int lr  = tid >> 4;           // loader row base
    const int lc4 = (tid & 15) << 2;    // loader col

    // load Q tile + K/V tile 0
    for (int p = 0; p < 4; p++) {
        const int r = lr + p * 16;
        float4 q4 = *(const float4*)(Qg + r * HD_ + lc4);
        Qs[r * FP_ + lc4 + 0] = q4.x; Qs[r * FP_ + lc4 + 1] = q4.y;
        Qs[r * FP_ + lc4 + 2] = q4.z; Qs[r * FP_ + lc4 + 3] = q4.w;
        float4 k4 = *(const float4*)(Kg + r * HD_ + lc4);
        Ks0[r * FP_ + lc4 + 0] = k4.x; Ks0[r * FP_ + lc4 + 1] = k4.y;
        Ks0[r * FP_ + lc4 + 2] = k4.z; Ks0[r * FP_ + lc4 + 3] = k4.w;
        float4 v4 = *(const float4*)(Vg + r * HD_ + lc4);
        Vs0[r * FP_ + lc4 + 0] = v4.x; Vs0[r * FP_ + lc4 + 1] = v4.y;
        Vs0[r * FP_ + lc4 + 2] = v4.z; Vs0[r * FP_ + lc4 + 3] = v4.w;
    }
    __syncthreads();

    float m_i[4], l_i[4], O[4][4];
#pragma unroll
    for (int i = 0; i < 4; i++) {
        m_i[i] = -INFINITY; l_i[i] = 0.0f;
#pragma unroll
        for (int j = 0; j < 4; j++) O[i][j] = 0.0f;
    }

    for (int kv = 0; kv <= qtile; kv++) {
        const int cur = kv & 1;
        float* Ks = cur ? Ks1 : Ks0;
        float* Vs = cur ? Vs1 : Vs0;

        // prefetch next K/V tile into registers (latency hidden by compute)
        float4 kst[4], vst[4];
        if (kv < qtile) {
            const float* Kt = Kg + (size_t)(kv + 1) * 64 * HD_;
            const float* Vt = Vg + (size_t)(kv + 1) * 64 * HD_;
#pragma unroll
            for (int p = 0; p < 4; p++) {
                const int r = lr + p * 16;
                kst[p] = *(const float4*)(Kt + r * HD_ + lc4);
                vst[p] = *(const float4*)(Vt + r * HD_ + lc4);
            }
        }

        // S = Q K^T (4x4 microtile)
        float s[4][4];
#pragma unroll
        for (int i = 0; i < 4; i++)
#pragma unroll
            for (int j = 0; j < 4; j++) s[i][j] = 0.0f;

#pragma unroll 8
        for (int k = 0; k < 64; k++) {
            float qv[4], kk[4];
#pragma unroll
            for (int i = 0; i < 4; i++) qv[i] = Qs[(tr + 16 * i) * FP_ + k];
#pragma unroll
            for (int j = 0; j < 4; j++) kk[j] = Ks[(tc + 16 * j) * FP_ + k];
#pragma unroll
            for (int i = 0; i < 4; i++)
#pragma unroll
                for (int j = 0; j < 4; j++)
                    s[i][j] = fmaf(qv[i], kk[j], s[i][j]);
        }

        const bool diag = (kv == qtile);
#pragma unroll
        for (int i = 0; i < 4; i++)
#pragma unroll
            for (int j = 0; j < 4; j++) {
                s[i][j] *= 0.125f;   // 1/sqrt(64)
                if (diag && (tc + 16 * j) > (tr + 16 * i)) s[i][j] = -1e30f;
            }

        // Online softmax, rowwise (16 lanes per row)
#pragma unroll
        for (int i = 0; i < 4; i++) {
            float rm = fmaxf(fmaxf(s[i][0], s[i][1]), fmaxf(s[i][2], s[i][3]));
#pragma unroll
            for (int off = 8; off > 0; off >>= 1)
                rm = fmaxf(rm, __shfl_xor_sync(0xffffffffu, rm, off, 16));
            const float mnew  = fmaxf(m_i[i], rm);
            const float alpha = __expf(m_i[i] - mnew);
            m_i[i] = mnew;
            float rs = 0.0f;
#pragma unroll
            for (int j = 0; j < 4; j++) {
                const float p = __expf(s[i][j] - mnew);
                s[i][j] = p;
                rs += p;
            }
#pragma unroll
            for (int off = 8; off > 0; off >>= 1)
                rs += __shfl_xor_sync(0xffffffffu, rs, off, 16);
            l_i[i] = l_i[i] * alpha + rs;
#pragma unroll
            for (int j = 0; j < 4; j++) {
                O[i][j] *= alpha;
                Ps[(tr + 16 * i) * FP_ + (tc + 16 * j)] = s[i][j];
            }
        }
        __syncthreads();

        // O += P @ V
#pragma unroll 8
        for (int c = 0; c < 64; c++) {
            float pv[4], vv[4];
#pragma unroll
            for (int i = 0; i < 4; i++) pv[i] = Ps[(tr + 16 * i) * FP_ + c];
#pragma unroll
            for (int j = 0; j < 4; j++) vv[j] = Vs[c * FP_ + tc + 16 * j];
#pragma unroll
            for (int i = 0; i < 4; i++)
#pragma unroll
                for (int j = 0; j < 4; j++)
                    O[i][j] = fmaf(pv[i], vv[j], O[i][j]);
        }

        // drain staged regs into the other buffer
        if (kv < qtile) {
            float* Kn = cur ? Ks0 : Ks1;
            float* Vn = cur ? Vs0 : Vs1;
#pragma unroll
            for (int p = 0; p < 4; p++) {
                const int r = lr + p * 16;
                Kn[r * FP_ + lc4 + 0] = kst[p].x; Kn[r * FP_ + lc4 + 1] = kst[p].y;
                Kn[r * FP_ + lc4 + 2] = kst[p].z; Kn[r * FP_ + lc4 + 3] = kst[p].w;
                Vn[r * FP_ + lc4 + 0] = vst[p].x; Vn[r * FP_ + lc4 + 1] = vst[p].y;
                Vn[r * FP_ + lc4 + 2] = vst[p].z; Vn[r * FP_ + lc4 + 3] = vst[p].w;
            }
        }
        __syncthreads();
    }

    // epilogue: att[b, t, h*64+d]
    const int b = bh >> 4;
    const int h = bh & 15;
#pragma unroll
    for (int i = 0; i < 4; i++) {
        const int trow = qtile * 64 + tr + 16 * i;
        const float inv_l = 1.0f / l_i[i];
#pragma unroll
        for (int j = 0; j < 4; j++) {
            g_att[(((size_t)b * T_ + trow) * H_ + h) * HD_ + tc + 16 * j] = O[i][j] * inv_l;
        }
    }
}

// ---------------------------------------------------------------------------
extern "C" void kernel_launch(void* const* d_in, const int* in_sizes, int n_in,
                              void* d_out, int out_size)
{
    const float* x     = (const float*)d_in[0];
    // d_in[1] = mask (causal, known statically — ignored)
    const float* w_qkv = (const float*)d_in[2];
    const float* w_out = (const float*)d_in[3];
    float* out = (float*)d_out;

    cudaFuncSetAttribute(flash_kernel,
                         cudaFuncAttributeMaxDynamicSharedMemorySize, FLASH_SMEM);

    // 1) qkv = x @ w_qkv  -> scatter to g_q/g_k/g_v
    dim3 g1(NQKV_ / 128, M_ / 128);
    sgemm_kernel<0><<<g1, 256>>>(x, w_qkv, nullptr, NQKV_, D_);

    // 2) RoPE on q, k
    rope_kernel<<<(B_ * H_ * T_ * 32) / 256, 256>>>();

    // 3) causal flash attention -> g_att
    flash_kernel<<<dim3(T_ / 64, B_ * H_), 256, FLASH_SMEM>>>();

    // 4) out = att @ w_out
    dim3 g2(D_ / 128, M_ / 128);
    sgemm_kernel<1><<<g2, 256>>>(nullptr, w_out, out, D_, D_);
}

// round 6
// speedup vs baseline: 1.1743x; 1.0962x over previous
#include <cuda_runtime.h>
#include <math.h>
#include <stdint.h>

// Problem constants
#define B_   2
#define H_   16
#define T_   2048
#define D_   1024
#define HD_  64
#define M_   (B_*T_)      // 4096 rows
#define NQKV_ (3*D_)      // 3072

// Scratch (device globals: allocation-free rule)
__device__ float g_q[B_*H_*T_*HD_];    // [B,H,T,hd]
__device__ float g_k[B_*H_*T_*HD_];
__device__ float g_v[B_*H_*T_*HD_];
__device__ float g_att[B_*T_*D_];      // [B,T,H*hd]

__device__ __forceinline__ uint32_t smem_u32(const void* p) {
    uint32_t a;
    asm("{ .reg .u64 t; cvta.to.shared.u64 t, %1; cvt.u32.u64 %0, t; }" : "=r"(a) : "l"(p));
    return a;
}
__device__ __forceinline__ void cp_async16(uint32_t dst, const void* src) {
    asm volatile("cp.async.cg.shared.global [%0], [%1], 16;" :: "r"(dst), "l"(src));
}
__device__ __forceinline__ void cp_commit() { asm volatile("cp.async.commit_group;" ::: "memory"); }
__device__ __forceinline__ void cp_wait0()  { asm volatile("cp.async.wait_group 0;" ::: "memory"); }

// ---------------------------------------------------------------------------
// SGEMM (unchanged from R5): C[M,N] = A[M,K] @ B[K,N], 128x128x16, 256 thr.
// ---------------------------------------------------------------------------
template<int MODE>
__global__ __launch_bounds__(256, 2)
void sgemm_kernel(const float* __restrict__ Ain, const float* __restrict__ Bw,
                  float* __restrict__ Cout, int N, int K)
{
    constexpr int BM = 128, BN = 128, BK = 16;
    __shared__ float As[2][BK][BM];   // transposed A tile
    __shared__ float Bs[2][BK][BN];

    const float* A = (MODE == 0) ? Ain : g_att;

    const int tid = threadIdx.x;
    const int bm  = blockIdx.y;
    const int bn  = blockIdx.x;
    const int tr  = tid >> 4;
    const int tc  = tid & 15;

    float acc[8][8];
#pragma unroll
    for (int i = 0; i < 8; i++)
#pragma unroll
        for (int j = 0; j < 8; j++) acc[i][j] = 0.0f;

    const int rowA = tid >> 2;
    const int colA = (tid & 3) << 2;
    const int rowB = tid >> 5;
    const int colB = (tid & 31) << 2;

    const float* Ab = A + (size_t)bm * BM * K;
    const float* Bb = Bw + (size_t)bn * BN;

    const uint32_t bs_base = smem_u32(&Bs[0][0][0]);
    const uint32_t bs_off0 = (uint32_t)((rowB * BN + colB) * 4);
    const uint32_t bs_off1 = (uint32_t)(((rowB + 8) * BN + colB) * 4);
    const uint32_t bs_buf  = (uint32_t)(BK * BN * 4);

    const int NT = K / BK;

    {
        float4 a0 = *(const float4*)(Ab + (size_t)rowA        * K + colA);
        float4 a1 = *(const float4*)(Ab + (size_t)(rowA + 64) * K + colA);
        cp_async16(bs_base + bs_off0, Bb + (size_t)rowB       * N + colB);
        cp_async16(bs_base + bs_off1, Bb + (size_t)(rowB + 8) * N + colB);
        cp_commit();
        As[0][colA + 0][rowA] = a0.x; As[0][colA + 1][rowA] = a0.y;
        As[0][colA + 2][rowA] = a0.z; As[0][colA + 3][rowA] = a0.w;
        As[0][colA + 0][rowA + 64] = a1.x; As[0][colA + 1][rowA + 64] = a1.y;
        As[0][colA + 2][rowA + 64] = a1.z; As[0][colA + 3][rowA + 64] = a1.w;
        cp_wait0();
        __syncthreads();
    }

    for (int t = 0; t < NT; t++) {
        const int buf = t & 1;

        float4 n0, n1;
        if (t + 1 < NT) {
            const int k0 = (t + 1) * BK;
            n0 = *(const float4*)(Ab + (size_t)rowA        * K + k0 + colA);
            n1 = *(const float4*)(Ab + (size_t)(rowA + 64) * K + k0 + colA);
            const uint32_t bdst = bs_base + (buf ^ 1) * bs_buf;
            cp_async16(bdst + bs_off0, Bb + (size_t)(k0 + rowB)     * N + colB);
            cp_async16(bdst + bs_off1, Bb + (size_t)(k0 + rowB + 8) * N + colB);
            cp_commit();
        }

#pragma unroll
        for (int k = 0; k < BK; k++) {
            float rm[8], rn[8];
            *(float4*)(rm)     = *(const float4*)&As[buf][k][tr * 8];
            *(float4*)(rm + 4) = *(const float4*)&As[buf][k][tr * 8 + 4];
            *(float4*)(rn)     = *(const float4*)&Bs[buf][k][tc * 8];
            *(float4*)(rn + 4) = *(const float4*)&Bs[buf][k][tc * 8 + 4];
#pragma unroll
            for (int i = 0; i < 8; i++)
#pragma unroll
                for (int j = 0; j < 8; j++)
                    acc[i][j] = fmaf(rm[i], rn[j], acc[i][j]);
        }

        if (t + 1 < NT) {
            const int nb = buf ^ 1;
            As[nb][colA + 0][rowA] = n0.x; As[nb][colA + 1][rowA] = n0.y;
            As[nb][colA + 2][rowA] = n0.z; As[nb][colA + 3][rowA] = n0.w;
            As[nb][colA + 0][rowA + 64] = n1.x; As[nb][colA + 1][rowA + 64] = n1.y;
            As[nb][colA + 2][rowA + 64] = n1.z; As[nb][colA + 3][rowA + 64] = n1.w;
            cp_wait0();
            __syncthreads();
        }
    }

#pragma unroll
    for (int i = 0; i < 8; i++) {
        const int r = bm * BM + tr * 8 + i;
#pragma unroll
        for (int j = 0; j < 8; j++) {
            const int c = bn * BN + tc * 8 + j;
            if (MODE == 0) {
                const int b    = r >> 11;
                const int t    = r & (T_ - 1);
                const int part = c >> 10;
                const int idx  = c & 1023;
                const int h    = idx >> 6;
                const int d    = idx & 63;
                float* dst = (part == 0) ? g_q : (part == 1) ? g_k : g_v;
                dst[(((size_t)b * H_ + h) * T_ + t) * HD_ + d] = acc[i][j];
            } else {
                Cout[(size_t)r * N + c] = acc[i][j];
            }
        }
    }
}

// ---------------------------------------------------------------------------
// RoPE (unchanged)
// ---------------------------------------------------------------------------
__global__ void rope_kernel()
{
    const int idx = blockIdx.x * blockDim.x + threadIdx.x;
    const int j  = idx & 31;
    const int t  = (idx >> 5) & (T_ - 1);
    const int bh = idx >> 16;

    const float f   = exp2f(-(float)j * (13.287712379549449f / 32.0f));
    float s, c;
    sincosf((float)t * f, &s, &c);

    const size_t base = ((size_t)bh * T_ + t) * HD_;
    float a0 = g_q[base + j], b0 = g_q[base + j + 32];
    g_q[base + j]      = a0 * c - b0 * s;
    g_q[base + j + 32] = b0 * c + a0 * s;
    float a1 = g_k[base + j], b1 = g_k[base + j + 32];
    g_k[base + j]      = a1 * c - b1 * s;
    g_k[base + j + 32] = b1 * c + a1 * s;
}

// ---------------------------------------------------------------------------
// Flash attention v2, causal, fp32. Br=Bc=128, 256 threads, 8x8 S microtile,
// float4 smem operand loads (FFMA:LDS ~9:1). V stored transposed for
// vectorized PV. 1 CTA/SM (171KB smem). Reverse-qtile launch for balance.
// Thread (tr,tc): rows {tr+16i}, S cols {tc+16j}, O cols {tc+16j, j<4}.
// ---------------------------------------------------------------------------
#define BRF  128
#define QP   68                       // Q/K smem pitch (floats, 16B aligned)
#define VP   132                      // Vt pitch
#define PPCH 132                      // P pitch
#define FLASH_SMEM ((2 * BRF * QP + HD_ * VP + BRF * PPCH) * (int)sizeof(float))

__global__ __launch_bounds__(256, 1)
void flash_kernel()
{
    extern __shared__ float sm[];
    float* Qs = sm;                    // [128][QP]
    float* Ks = Qs + BRF * QP;         // [128][QP]
    float* Vt = Ks + BRF * QP;         // [64][VP]  (transposed: Vt[d][c])
    float* Ps = Vt + HD_ * VP;         // [128][PPCH]

    const int tid = threadIdx.x;
    const int tr  = tid >> 4;          // 0..15
    const int tc  = tid & 15;          // 0..15
    const int qtile = (int)gridDim.x - 1 - (int)blockIdx.x;  // big tiles first
    const int bh    = blockIdx.y;

    const float* Qg = g_q + ((size_t)bh * T_ + (size_t)qtile * BRF) * HD_;
    const float* Kg = g_k + (size_t)bh * T_ * HD_;
    const float* Vg = g_v + (size_t)bh * T_ * HD_;

    // load Q tile (128x64)
#pragma unroll
    for (int p = 0; p < 8; p++) {
        const int idx = tid + p * 256;
        const int r  = idx >> 4;
        const int c4 = (idx & 15) << 2;
        float4 q4 = *(const float4*)(Qg + r * HD_ + c4);
        *(float4*)&Qs[r * QP + c4] = q4;
    }

    float m_i[8], l_i[8], O[8][4];
#pragma unroll
    for (int i = 0; i < 8; i++) {
        m_i[i] = -INFINITY; l_i[i] = 0.0f;
#pragma unroll
        for (int j = 0; j < 4; j++) O[i][j] = 0.0f;
    }

    for (int kv = 0; kv <= qtile; kv++) {
        __syncthreads();   // prev iter done with Ks/Vt
        const float* Kt = Kg + (size_t)kv * BRF * HD_;
        const float* Vv = Vg + (size_t)kv * BRF * HD_;
#pragma unroll
        for (int p = 0; p < 8; p++) {
            const int idx = tid + p * 256;
            const int r  = idx >> 4;
            const int c4 = (idx & 15) << 2;
            float4 k4 = *(const float4*)(Kt + r * HD_ + c4);
            *(float4*)&Ks[r * QP + c4] = k4;
            float4 v4 = *(const float4*)(Vv + r * HD_ + c4);
            Vt[(c4 + 0) * VP + r] = v4.x;
            Vt[(c4 + 1) * VP + r] = v4.y;
            Vt[(c4 + 2) * VP + r] = v4.z;
            Vt[(c4 + 3) * VP + r] = v4.w;
        }
        __syncthreads();

        // S = Q K^T, 8x8 microtile, float4 along d
        float s[8][8];
#pragma unroll
        for (int i = 0; i < 8; i++)
#pragma unroll
            for (int j = 0; j < 8; j++) s[i][j] = 0.0f;

#pragma unroll
        for (int d0 = 0; d0 < HD_; d0 += 4) {
            float4 qv[8];
#pragma unroll
            for (int i = 0; i < 8; i++)
                qv[i] = *(const float4*)&Qs[(tr + 16 * i) * QP + d0];
#pragma unroll
            for (int j = 0; j < 8; j++) {
                const float4 kk = *(const float4*)&Ks[(tc + 16 * j) * QP + d0];
#pragma unroll
                for (int i = 0; i < 8; i++) {
                    s[i][j] = fmaf(qv[i].x, kk.x, s[i][j]);
                    s[i][j] = fmaf(qv[i].y, kk.y, s[i][j]);
                    s[i][j] = fmaf(qv[i].z, kk.z, s[i][j]);
                    s[i][j] = fmaf(qv[i].w, kk.w, s[i][j]);
                }
            }
        }

        const bool diag = (kv == qtile);
#pragma unroll
        for (int i = 0; i < 8; i++)
#pragma unroll
            for (int j = 0; j < 8; j++) {
                s[i][j] *= 0.125f;   // 1/sqrt(64)
                if (diag && (tc + 16 * j) > (tr + 16 * i)) s[i][j] = -1e30f;
            }

        // Online softmax, rowwise (16 lanes per row via width-16 shuffles)
#pragma unroll
        for (int i = 0; i < 8; i++) {
            float rm = s[i][0];
#pragma unroll
            for (int j = 1; j < 8; j++) rm = fmaxf(rm, s[i][j]);
#pragma unroll
            for (int off = 8; off > 0; off >>= 1)
                rm = fmaxf(rm, __shfl_xor_sync(0xffffffffu, rm, off, 16));
            const float mnew  = fmaxf(m_i[i], rm);
            const float alpha = __expf(m_i[i] - mnew);
            m_i[i] = mnew;
            float rs = 0.0f;
#pragma unroll
            for (int j = 0; j < 8; j++) {
                const float p = __expf(s[i][j] - mnew);
                s[i][j] = p;
                rs += p;
            }
#pragma unroll
            for (int off = 8; off > 0; off >>= 1)
                rs += __shfl_xor_sync(0xffffffffu, rs, off, 16);
            l_i[i] = l_i[i] * alpha + rs;
#pragma unroll
            for (int j = 0; j < 4; j++) O[i][j] *= alpha;
#pragma unroll
            for (int j = 0; j < 8; j++)
                Ps[(tr + 16 * i) * PPCH + (tc + 16 * j)] = s[i][j];
        }
        __syncthreads();

        // O += P @ V  (float4 along c via transposed V)
#pragma unroll 4
        for (int c0 = 0; c0 < BRF; c0 += 4) {
            float4 pv[8];
#pragma unroll
            for (int i = 0; i < 8; i++)
                pv[i] = *(const float4*)&Ps[(tr + 16 * i) * PPCH + c0];
#pragma unroll
            for (int j = 0; j < 4; j++) {
                const float4 vv = *(const float4*)&Vt[(tc + 16 * j) * VP + c0];
#pragma unroll
                for (int i = 0; i < 8; i++) {
                    O[i][j] = fmaf(pv[i].x, vv.x, O[i][j]);
                    O[i][j] = fmaf(pv[i].y, vv.y, O[i][j]);
                    O[i][j] = fmaf(pv[i].z, vv.z, O[i][j]);
                    O[i][j] = fmaf(pv[i].w, vv.w, O[i][j]);
                }
            }
        }
    }

    // epilogue: att[b, t, h*64+d]
    const int b = bh >> 4;
    const int h = bh & 15;
#pragma unroll
    for (int i = 0; i < 8; i++) {
        const int trow = qtile * BRF + tr + 16 * i;
        const float inv_l = 1.0f / l_i[i];
#pragma unroll
        for (int j = 0; j < 4; j++) {
            g_att[(((size_t)b * T_ + trow) * H_ + h) * HD_ + tc + 16 * j] = O[i][j] * inv_l;
        }
    }
}

// ---------------------------------------------------------------------------
extern "C" void kernel_launch(void* const* d_in, const int* in_sizes, int n_in,
                              void* d_out, int out_size)
{
    const float* x     = (const float*)d_in[0];
    // d_in[1] = mask (causal, known statically — ignored)
    const float* w_qkv = (const float*)d_in[2];
    const float* w_out = (const float*)d_in[3];
    float* out = (float*)d_out;

    cudaFuncSetAttribute(flash_kernel,
                         cudaFuncAttributeMaxDynamicSharedMemorySize, FLASH_SMEM);

    // 1) qkv = x @ w_qkv  -> scatter to g_q/g_k/g_v
    dim3 g1(NQKV_ / 128, M_ / 128);
    sgemm_kernel<0><<<g1, 256>>>(x, w_qkv, nullptr, NQKV_, D_);

    // 2) RoPE on q, k
    rope_kernel<<<(B_ * H_ * T_ * 32) / 256, 256>>>();

    // 3) causal flash attention -> g_att
    flash_kernel<<<dim3(T_ / BRF, B_ * H_), 256, FLASH_SMEM>>>();

    // 4) out = att @ w_out
    dim3 g2(D_ / 128, M_ / 128);
    sgemm_kernel<1><<<g2, 256>>>(nullptr, w_out, out, D_, D_);
}

// round 7
// speedup vs baseline: 1.2053x; 1.0264x over previous
#include <cuda_runtime.h>
#include <math.h>
#include <stdint.h>

// Problem constants
#define B_   2
#define H_   16
#define T_   2048
#define D_   1024
#define HD_  64
#define M_   (B_*T_)      // 4096 rows
#define NQKV_ (3*D_)      // 3072

typedef unsigned long long ull;

// Scratch (device globals: allocation-free rule)
__device__ float g_q[B_*H_*T_*HD_];    // [B,H,T,hd]
__device__ float g_k[B_*H_*T_*HD_];
__device__ float g_v[B_*H_*T_*HD_];
__device__ float g_att[B_*T_*D_];      // [B,T,H*hd]

__device__ __forceinline__ uint32_t smem_u32(const void* p) {
    uint32_t a;
    asm("{ .reg .u64 t; cvta.to.shared.u64 t, %1; cvt.u32.u64 %0, t; }" : "=r"(a) : "l"(p));
    return a;
}
__device__ __forceinline__ void cp_async16(uint32_t dst, const void* src) {
    asm volatile("cp.async.cg.shared.global [%0], [%1], 16;" :: "r"(dst), "l"(src));
}
__device__ __forceinline__ void cp_commit() { asm volatile("cp.async.commit_group;" ::: "memory"); }
__device__ __forceinline__ void cp_wait0()  { asm volatile("cp.async.wait_group 0;" ::: "memory"); }

// ---- packed f32x2 helpers (Blackwell family PTX, sm_100+) ----
__device__ __forceinline__ ull pack2(float x, float y) {
    ull r;
    asm("mov.b64 %0, {%1, %2};" : "=l"(r) : "f"(x), "f"(y));
    return r;
}
__device__ __forceinline__ void ffma2(ull& d, ull a, ull b) {
    asm("fma.rn.f32x2 %0, %1, %2, %0;" : "+l"(d) : "l"(a), "l"(b));
}

// ---------------------------------------------------------------------------
// SGEMM with f32x2 inner loop: C[M,N] = A[M,K] @ B[K,N], 128x128x16, 256 thr.
// acc packed along j (4 x f32x2 per row of the 8x8 microtile).
// MODE 0: A = x, scatter epilogue into g_q/g_k/g_v; MODE 1: plain store.
// ---------------------------------------------------------------------------
template<int MODE>
__global__ __launch_bounds__(256, 2)
void sgemm_kernel(const float* __restrict__ Ain, const float* __restrict__ Bw,
                  float* __restrict__ Cout, int N, int K)
{
    constexpr int BM = 128, BN = 128, BK = 16;
    __shared__ float As[2][BK][BM];   // transposed A tile
    __shared__ float Bs[2][BK][BN];

    const float* A = (MODE == 0) ? Ain : g_att;

    const int tid = threadIdx.x;
    const int bm  = blockIdx.y;
    const int bn  = blockIdx.x;
    const int tr  = tid >> 4;
    const int tc  = tid & 15;

    ull acc2[8][4];
#pragma unroll
    for (int i = 0; i < 8; i++)
#pragma unroll
        for (int j = 0; j < 4; j++) acc2[i][j] = 0ULL;

    const int rowA = tid >> 2;
    const int colA = (tid & 3) << 2;
    const int rowB = tid >> 5;
    const int colB = (tid & 31) << 2;

    const float* Ab = A + (size_t)bm * BM * K;
    const float* Bb = Bw + (size_t)bn * BN;

    const uint32_t bs_base = smem_u32(&Bs[0][0][0]);
    const uint32_t bs_off0 = (uint32_t)((rowB * BN + colB) * 4);
    const uint32_t bs_off1 = (uint32_t)(((rowB + 8) * BN + colB) * 4);
    const uint32_t bs_buf  = (uint32_t)(BK * BN * 4);

    const int NT = K / BK;

    {
        float4 a0 = *(const float4*)(Ab + (size_t)rowA        * K + colA);
        float4 a1 = *(const float4*)(Ab + (size_t)(rowA + 64) * K + colA);
        cp_async16(bs_base + bs_off0, Bb + (size_t)rowB       * N + colB);
        cp_async16(bs_base + bs_off1, Bb + (size_t)(rowB + 8) * N + colB);
        cp_commit();
        As[0][colA + 0][rowA] = a0.x; As[0][colA + 1][rowA] = a0.y;
        As[0][colA + 2][rowA] = a0.z; As[0][colA + 3][rowA] = a0.w;
        As[0][colA + 0][rowA + 64] = a1.x; As[0][colA + 1][rowA + 64] = a1.y;
        As[0][colA + 2][rowA + 64] = a1.z; As[0][colA + 3][rowA + 64] = a1.w;
        cp_wait0();
        __syncthreads();
    }

    for (int t = 0; t < NT; t++) {
        const int buf = t & 1;

        float4 n0, n1;
        if (t + 1 < NT) {
            const int k0 = (t + 1) * BK;
            n0 = *(const float4*)(Ab + (size_t)rowA        * K + k0 + colA);
            n1 = *(const float4*)(Ab + (size_t)(rowA + 64) * K + k0 + colA);
            const uint32_t bdst = bs_base + (buf ^ 1) * bs_buf;
            cp_async16(bdst + bs_off0, Bb + (size_t)(k0 + rowB)     * N + colB);
            cp_async16(bdst + bs_off1, Bb + (size_t)(k0 + rowB + 8) * N + colB);
            cp_commit();
        }

#pragma unroll
        for (int k = 0; k < BK; k++) {
            float4 m0 = *(const float4*)&As[buf][k][tr * 8];
            float4 m1 = *(const float4*)&As[buf][k][tr * 8 + 4];
            float4 b0 = *(const float4*)&Bs[buf][k][tc * 8];
            float4 b1 = *(const float4*)&Bs[buf][k][tc * 8 + 4];

            ull rn2[4];
            rn2[0] = pack2(b0.x, b0.y); rn2[1] = pack2(b0.z, b0.w);
            rn2[2] = pack2(b1.x, b1.y); rn2[3] = pack2(b1.z, b1.w);

            ull rm2[8];
            rm2[0] = pack2(m0.x, m0.x); rm2[1] = pack2(m0.y, m0.y);
            rm2[2] = pack2(m0.z, m0.z); rm2[3] = pack2(m0.w, m0.w);
            rm2[4] = pack2(m1.x, m1.x); rm2[5] = pack2(m1.y, m1.y);
            rm2[6] = pack2(m1.z, m1.z); rm2[7] = pack2(m1.w, m1.w);

#pragma unroll
            for (int i = 0; i < 8; i++)
#pragma unroll
                for (int j = 0; j < 4; j++)
                    ffma2(acc2[i][j], rm2[i], rn2[j]);
        }

        if (t + 1 < NT) {
            const int nb = buf ^ 1;
            As[nb][colA + 0][rowA] = n0.x; As[nb][colA + 1][rowA] = n0.y;
            As[nb][colA + 2][rowA] = n0.z; As[nb][colA + 3][rowA] = n0.w;
            As[nb][colA + 0][rowA + 64] = n1.x; As[nb][colA + 1][rowA + 64] = n1.y;
            As[nb][colA + 2][rowA + 64] = n1.z; As[nb][colA + 3][rowA + 64] = n1.w;
            cp_wait0();
            __syncthreads();
        }
    }

    // Epilogue: acc2[i][j2] holds cols (tc*8 + 2*j2, +1)
#pragma unroll
    for (int i = 0; i < 8; i++) {
        const int r = bm * BM + tr * 8 + i;
#pragma unroll
        for (int j = 0; j < 4; j++) {
            const int c = bn * BN + tc * 8 + 2 * j;
            const float2 v = *(float2*)&acc2[i][j];
            if (MODE == 0) {
                const int b    = r >> 11;
                const int t    = r & (T_ - 1);
                const int part = c >> 10;
                const int idx  = c & 1023;
                const int h    = idx >> 6;
                const int d    = idx & 63;
                float* dst = (part == 0) ? g_q : (part == 1) ? g_k : g_v;
                *(float2*)(dst + (((size_t)b * H_ + h) * T_ + t) * HD_ + d) = v;
            } else {
                *(float2*)(Cout + (size_t)r * N + c) = v;
            }
        }
    }
}

// ---------------------------------------------------------------------------
// RoPE (unchanged)
// ---------------------------------------------------------------------------
__global__ void rope_kernel()
{
    const int idx = blockIdx.x * blockDim.x + threadIdx.x;
    const int j  = idx & 31;
    const int t  = (idx >> 5) & (T_ - 1);
    const int bh = idx >> 16;

    const float f   = exp2f(-(float)j * (13.287712379549449f / 32.0f));
    float s, c;
    sincosf((float)t * f, &s, &c);

    const size_t base = ((size_t)bh * T_ + t) * HD_;
    float a0 = g_q[base + j], b0 = g_q[base + j + 32];
    g_q[base + j]      = a0 * c - b0 * s;
    g_q[base + j + 32] = b0 * c + a0 * s;
    float a1 = g_k[base + j], b1 = g_k[base + j + 32];
    g_k[base + j]      = a1 * c - b1 * s;
    g_k[base + j + 32] = b1 * c + a1 * s;
}

// ---------------------------------------------------------------------------
// Flash attention v2 (unchanged from R6). Br=Bc=128, 256 threads.
// ---------------------------------------------------------------------------
#define BRF  128
#define QP   68
#define VP   132
#define PPCH 132
#define FLASH_SMEM ((2 * BRF * QP + HD_ * VP + BRF * PPCH) * (int)sizeof(float))

__global__ __launch_bounds__(256, 1)
void flash_kernel()
{
    extern __shared__ float sm[];
    float* Qs = sm;
    float* Ks = Qs + BRF * QP;
    float* Vt = Ks + BRF * QP;
    float* Ps = Vt + HD_ * VP;

    const int tid = threadIdx.x;
    const int tr  = tid >> 4;
    const int tc  = tid & 15;
    const int qtile = (int)gridDim.x - 1 - (int)blockIdx.x;
    const int bh    = blockIdx.y;

    const float* Qg = g_q + ((size_t)bh * T_ + (size_t)qtile * BRF) * HD_;
    const float* Kg = g_k + (size_t)bh * T_ * HD_;
    const float* Vg = g_v + (size_t)bh * T_ * HD_;

#pragma unroll
    for (int p = 0; p < 8; p++) {
        const int idx = tid + p * 256;
        const int r  = idx >> 4;
        const int c4 = (idx & 15) << 2;
        float4 q4 = *(const float4*)(Qg + r * HD_ + c4);
        *(float4*)&Qs[r * QP + c4] = q4;
    }

    float m_i[8], l_i[8], O[8][4];
#pragma unroll
    for (int i = 0; i < 8; i++) {
        m_i[i] = -INFINITY; l_i[i] = 0.0f;
#pragma unroll
        for (int j = 0; j < 4; j++) O[i][j] = 0.0f;
    }

    for (int kv = 0; kv <= qtile; kv++) {
        __syncthreads();
        const float* Kt = Kg + (size_t)kv * BRF * HD_;
        const float* Vv = Vg + (size_t)kv * BRF * HD_;
#pragma unroll
        for (int p = 0; p < 8; p++) {
            const int idx = tid + p * 256;
            const int r  = idx >> 4;
            const int c4 = (idx & 15) << 2;
            float4 k4 = *(const float4*)(Kt + r * HD_ + c4);
            *(float4*)&Ks[r * QP + c4] = k4;
            float4 v4 = *(const float4*)(Vv + r * HD_ + c4);
            Vt[(c4 + 0) * VP + r] = v4.x;
            Vt[(c4 + 1) * VP + r] = v4.y;
            Vt[(c4 + 2) * VP + r] = v4.z;
            Vt[(c4 + 3) * VP + r] = v4.w;
        }
        __syncthreads();

        float s[8][8];
#pragma unroll
        for (int i = 0; i < 8; i++)
#pragma unroll
            for (int j = 0; j < 8; j++) s[i][j] = 0.0f;

#pragma unroll
        for (int d0 = 0; d0 < HD_; d0 += 4) {
            float4 qv[8];
#pragma unroll
            for (int i = 0; i < 8; i++)
                qv[i] = *(const float4*)&Qs[(tr + 16 * i) * QP + d0];
#pragma unroll
            for (int j = 0; j < 8; j++) {
                const float4 kk = *(const float4*)&Ks[(tc + 16 * j) * QP + d0];
#pragma unroll
                for (int i = 0; i < 8; i++) {
                    s[i][j] = fmaf(qv[i].x, kk.x, s[i][j]);
                    s[i][j] = fmaf(qv[i].y, kk.y, s[i][j]);
                    s[i][j] = fmaf(qv[i].z, kk.z, s[i][j]);
                    s[i][j] = fmaf(qv[i].w, kk.w, s[i][j]);
                }
            }
        }

        const bool diag = (kv == qtile);
#pragma unroll
        for (int i = 0; i < 8; i++)
#pragma unroll
            for (int j = 0; j < 8; j++) {
                s[i][j] *= 0.125f;
                if (diag && (tc + 16 * j) > (tr + 16 * i)) s[i][j] = -1e30f;
            }

#pragma unroll
        for (int i = 0; i < 8; i++) {
            float rm = s[i][0];
#pragma unroll
            for (int j = 1; j < 8; j++) rm = fmaxf(rm, s[i][j]);
#pragma unroll
            for (int off = 8; off > 0; off >>= 1)
                rm = fmaxf(rm, __shfl_xor_sync(0xffffffffu, rm, off, 16));
            const float mnew  = fmaxf(m_i[i], rm);
            const float alpha = __expf(m_i[i] - mnew);
            m_i[i] = mnew;
            float rs = 0.0f;
#pragma unroll
            for (int j = 0; j < 8; j++) {
                const float p = __expf(s[i][j] - mnew);
                s[i][j] = p;
                rs += p;
            }
#pragma unroll
            for (int off = 8; off > 0; off >>= 1)
                rs += __shfl_xor_sync(0xffffffffu, rs, off, 16);
            l_i[i] = l_i[i] * alpha + rs;
#pragma unroll
            for (int j = 0; j < 4; j++) O[i][j] *= alpha;
#pragma unroll
            for (int j = 0; j < 8; j++)
                Ps[(tr + 16 * i) * PPCH + (tc + 16 * j)] = s[i][j];
        }
        __syncthreads();

#pragma unroll 4
        for (int c0 = 0; c0 < BRF; c0 += 4) {
            float4 pv[8];
#pragma unroll
            for (int i = 0; i < 8; i++)
                pv[i] = *(const float4*)&Ps[(tr + 16 * i) * PPCH + c0];
#pragma unroll
            for (int j = 0; j < 4; j++) {
                const float4 vv = *(const float4*)&Vt[(tc + 16 * j) * VP + c0];
#pragma unroll
                for (int i = 0; i < 8; i++) {
                    O[i][j] = fmaf(pv[i].x, vv.x, O[i][j]);
                    O[i][j] = fmaf(pv[i].y, vv.y, O[i][j]);
                    O[i][j] = fmaf(pv[i].z, vv.z, O[i][j]);
                    O[i][j] = fmaf(pv[i].w, vv.w, O[i][j]);
                }
            }
        }
    }

    const int b = bh >> 4;
    const int h = bh & 15;
#pragma unroll
    for (int i = 0; i < 8; i++) {
        const int trow = qtile * BRF + tr + 16 * i;
        const float inv_l = 1.0f / l_i[i];
#pragma unroll
        for (int j = 0; j < 4; j++) {
            g_att[(((size_t)b * T_ + trow) * H_ + h) * HD_ + tc + 16 * j] = O[i][j] * inv_l;
        }
    }
}

// ---------------------------------------------------------------------------
extern "C" void kernel_launch(void* const* d_in, const int* in_sizes, int n_in,
                              void* d_out, int out_size)
{
    const float* x     = (const float*)d_in[0];
    // d_in[1] = mask (causal, known statically — ignored)
    const float* w_qkv = (const float*)d_in[2];
    const float* w_out = (const float*)d_in[3];
    float* out = (float*)d_out;

    cudaFuncSetAttribute(flash_kernel,
                         cudaFuncAttributeMaxDynamicSharedMemorySize, FLASH_SMEM);

    // 1) qkv = x @ w_qkv  -> scatter to g_q/g_k/g_v
    dim3 g1(NQKV_ / 128, M_ / 128);
    sgemm_kernel<0><<<g1, 256>>>(x, w_qkv, nullptr, NQKV_, D_);

    // 2) RoPE on q, k
    rope_kernel<<<(B_ * H_ * T_ * 32) / 256, 256>>>();

    // 3) causal flash attention -> g_att
    flash_kernel<<<dim3(T_ / BRF, B_ * H_), 256, FLASH_SMEM>>>();

    // 4) out = att @ w_out
    dim3 g2(D_ / 128, M_ / 128);
    sgemm_kernel<1><<<g2, 256>>>(nullptr, w_out, out, D_, D_);
}

// round 8
// speedup vs baseline: 1.7454x; 1.4481x over previous
#include <cuda_runtime.h>
#include <cuda_bf16.h>
#include <math.h>
#include <stdint.h>

// Problem constants
#define B_   2
#define H_   16
#define T_   2048
#define D_   1024
#define HD_  64
#define M_   (B_*T_)      // 4096 rows
#define NQKV_ (3*D_)      // 3072
#define K_   1024

// Scratch (device globals: allocation-free rule)
__device__ float g_q[B_*H_*T_*HD_];
__device__ float g_k[B_*H_*T_*HD_];
__device__ float g_v[B_*H_*T_*HD_];
__device__ float g_att[B_*T_*D_];

// bf16 split operands
__device__ __align__(16) __nv_bfloat16 g_xh[M_*D_],    g_xl[M_*D_];
__device__ __align__(16) __nv_bfloat16 g_wqkvTh[NQKV_*D_], g_wqkvTl[NQKV_*D_];
__device__ __align__(16) __nv_bfloat16 g_woutTh[D_*D_],   g_woutTl[D_*D_];
__device__ __align__(16) __nv_bfloat16 g_atth[M_*D_],  g_attl[M_*D_];

__device__ __forceinline__ uint32_t smem_u32(const void* p) {
    uint32_t a;
    asm("{ .reg .u64 t; cvta.to.shared.u64 t, %1; cvt.u32.u64 %0, t; }" : "=r"(a) : "l"(p));
    return a;
}
__device__ __forceinline__ void cp_async16(uint32_t dst, const void* src) {
    asm volatile("cp.async.cg.shared.global [%0], [%1], 16;" :: "r"(dst), "l"(src));
}
__device__ __forceinline__ void cp_commit() { asm volatile("cp.async.commit_group;" ::: "memory"); }
__device__ __forceinline__ void cp_wait0()  { asm volatile("cp.async.wait_group 0;" ::: "memory"); }
__device__ __forceinline__ uint32_t lds32(uint32_t a) {
    uint32_t v;
    asm volatile("ld.shared.b32 %0, [%1];" : "=r"(v) : "r"(a));
    return v;
}
__device__ __forceinline__ void mma_bf16(float c[4], const uint32_t a[4], const uint32_t b[2]) {
    asm volatile(
        "mma.sync.aligned.m16n8k16.row.col.f32.bf16.bf16.f32 "
        "{%0,%1,%2,%3}, {%4,%5,%6,%7}, {%8,%9}, {%0,%1,%2,%3};"
        : "+f"(c[0]), "+f"(c[1]), "+f"(c[2]), "+f"(c[3])
        : "r"(a[0]), "r"(a[1]), "r"(a[2]), "r"(a[3]), "r"(b[0]), "r"(b[1]));
}

__device__ __forceinline__ void split1(float v, __nv_bfloat16& h, __nv_bfloat16& l) {
    h = __float2bfloat16(v);
    l = __float2bfloat16(v - __bfloat162float(h));
}

// ---------------------------------------------------------------------------
// split4: fp32[n] -> bf16 hi[n], lo[n]   (vectorized x4)
// ---------------------------------------------------------------------------
__global__ void split4_kernel(const float4* __restrict__ src,
                              __nv_bfloat162* __restrict__ h,
                              __nv_bfloat162* __restrict__ l, int n4)
{
    const int i = blockIdx.x * blockDim.x + threadIdx.x;
    if (i >= n4) return;
    const float4 v = src[i];
    __nv_bfloat16 hx, lx, hy, ly, hz, lz, hw, lw;
    split1(v.x, hx, lx); split1(v.y, hy, ly);
    split1(v.z, hz, lz); split1(v.w, hw, lw);
    h[2*i]   = __nv_bfloat162(hx, hy);
    h[2*i+1] = __nv_bfloat162(hz, hw);
    l[2*i]   = __nv_bfloat162(lx, ly);
    l[2*i+1] = __nv_bfloat162(lz, lw);
}

// ---------------------------------------------------------------------------
// splitT: fp32 src[R][C] -> bf16 hT[C][R], lT[C][R]  (transpose + split)
// ---------------------------------------------------------------------------
__global__ void splitT_kernel(const float* __restrict__ src,
                              __nv_bfloat16* __restrict__ hT,
                              __nv_bfloat16* __restrict__ lT, int R, int C)
{
    __shared__ float tile[32][33];
    const int bx = blockIdx.x * 32, by = blockIdx.y * 32;
    const int tx = threadIdx.x, ty = threadIdx.y;   // 32 x 8
#pragma unroll
    for (int i = 0; i < 32; i += 8)
        tile[ty + i][tx] = src[(size_t)(by + ty + i) * C + bx + tx];
    __syncthreads();
#pragma unroll
    for (int i = 0; i < 32; i += 8) {
        const float v = tile[tx][ty + i];
        __nv_bfloat16 h, l;
        split1(v, h, l);
        const size_t o = (size_t)(bx + ty + i) * R + by + tx;
        hT[o] = h; lT[o] = l;
    }
}

// ---------------------------------------------------------------------------
// bf16 split-GEMM: C[M,N] = A[M,K] @ Bt[N,K]^T  (3 mmas: hh + lh + hl)
// 128x128 block, BK=32, 8 warps (2x4), warp tile 64x32, m16n8k16.
// smem: per buffer {Ah,Al,Bh,Bl} 128x32 bf16 @ pitch 40 (conflict-free frags).
// MODE 0: scatter into g_q/g_k/g_v; MODE 1: plain store.
// ---------------------------------------------------------------------------
#define PB    40                       // smem pitch in bf16 (80 bytes)
#define MATB  (128 * PB * 2)           // 10240 bytes per matrix
#define BUFB  (4 * MATB)               // 40960 bytes per buffer
#define BGEMM_SMEM (2 * BUFB)          // 81920

template<int MODE>
__global__ __launch_bounds__(256, 2)
void bgemm(const __nv_bfloat16* __restrict__ Ah, const __nv_bfloat16* __restrict__ Al,
           const __nv_bfloat16* __restrict__ Bh, const __nv_bfloat16* __restrict__ Bl,
           float* __restrict__ Cout, int N, int K)
{
    extern __shared__ char smc[];
    const uint32_t sb = smem_u32(smc);

    const int tid  = threadIdx.x;
    const int wid  = tid >> 5;
    const int lane = tid & 31;
    const int g    = lane >> 2;        // 0..7
    const int tig  = lane & 3;         // 0..3
    const int warp_m = wid >> 2;       // 0..1
    const int warp_n = wid & 3;        // 0..3
    const int bm = blockIdx.y;
    const int bn = blockIdx.x;

    const char* gsrc[4] = {
        (const char*)(Ah + (size_t)bm * 128 * K),
        (const char*)(Al + (size_t)bm * 128 * K),
        (const char*)(Bh + (size_t)bn * 128 * K),
        (const char*)(Bl + (size_t)bn * 128 * K)
    };
    const size_t grs = (size_t)K * 2;   // global row stride bytes

    float acc[4][4][4];
#pragma unroll
    for (int i = 0; i < 4; i++)
#pragma unroll
        for (int j = 0; j < 4; j++)
#pragma unroll
            for (int e = 0; e < 4; e++) acc[i][j][e] = 0.0f;

    const int NT = K / 32;

    // prologue: tile 0 -> buf 0
#pragma unroll
    for (int p = 0; p < 8; p++) {
        const int c   = tid + p * 256;
        const int mat = c >> 9;
        const int r   = (c >> 2) & 127;
        const int q   = (c & 3) * 16;
        cp_async16(sb + mat * MATB + r * (PB * 2) + q,
                   gsrc[mat] + (size_t)r * grs + q);
    }
    cp_commit();
    cp_wait0();
    __syncthreads();

    for (int t = 0; t < NT; t++) {
        const int buf = t & 1;

        if (t + 1 < NT) {
            const uint32_t db = sb + (buf ^ 1) * BUFB;
            const size_t kb = (size_t)(t + 1) * 64;
#pragma unroll
            for (int p = 0; p < 8; p++) {
                const int c   = tid + p * 256;
                const int mat = c >> 9;
                const int r   = (c >> 2) & 127;
                const int q   = (c & 3) * 16;
                cp_async16(db + mat * MATB + r * (PB * 2) + q,
                           gsrc[mat] + (size_t)r * grs + kb + q);
            }
            cp_commit();
        }

        const uint32_t base = sb + buf * BUFB;
#pragma unroll
        for (int ks = 0; ks < 2; ks++) {
            const uint32_t ko = ks * 32 + tig * 4;   // byte offset along k

            uint32_t ah[4][4], al[4][4], bh[4][2], bl[4][2];
#pragma unroll
            for (int i = 0; i < 4; i++) {
                const uint32_t ab = base + (warp_m * 64 + i * 16 + g) * (PB * 2) + ko;
                ah[i][0] = lds32(ab);       ah[i][1] = lds32(ab + 8 * PB * 2);
                ah[i][2] = lds32(ab + 16);  ah[i][3] = lds32(ab + 8 * PB * 2 + 16);
            }
#pragma unroll
            for (int j = 0; j < 4; j++) {
                const uint32_t bb = base + 2 * MATB + (warp_n * 32 + j * 8 + g) * (PB * 2) + ko;
                bh[j][0] = lds32(bb);       bh[j][1] = lds32(bb + 16);
            }
#pragma unroll
            for (int i = 0; i < 4; i++)
#pragma unroll
                for (int j = 0; j < 4; j++)
                    mma_bf16(acc[i][j], ah[i], bh[j]);     // hh

#pragma unroll
            for (int i = 0; i < 4; i++) {
                const uint32_t ab = base + MATB + (warp_m * 64 + i * 16 + g) * (PB * 2) + ko;
                al[i][0] = lds32(ab);       al[i][1] = lds32(ab + 8 * PB * 2);
                al[i][2] = lds32(ab + 16);  al[i][3] = lds32(ab + 8 * PB * 2 + 16);
            }
#pragma unroll
            for (int i = 0; i < 4; i++)
#pragma unroll
                for (int j = 0; j < 4; j++)
                    mma_bf16(acc[i][j], al[i], bh[j]);     // lh

#pragma unroll
            for (int j = 0; j < 4; j++) {
                const uint32_t bb = base + 3 * MATB + (warp_n * 32 + j * 8 + g) * (PB * 2) + ko;
                bl[j][0] = lds32(bb);       bl[j][1] = lds32(bb + 16);
            }
#pragma unroll
            for (int i = 0; i < 4; i++)
#pragma unroll
                for (int j = 0; j < 4; j++)
                    mma_bf16(acc[i][j], ah[i], bl[j]);     // hl
        }

        if (t + 1 < NT) cp_wait0();
        __syncthreads();
    }

    // Epilogue: thread (g,tig), tile (i,j): rows r0,r0+8; cols c0,c0+1
#pragma unroll
    for (int i = 0; i < 4; i++) {
        const int r0 = bm * 128 + warp_m * 64 + i * 16 + g;
#pragma unroll
        for (int j = 0; j < 4; j++) {
            const int c0 = bn * 128 + warp_n * 32 + j * 8 + tig * 2;
#pragma unroll
            for (int half = 0; half < 2; half++) {
                const int r = r0 + half * 8;
                const float2 v = make_float2(acc[i][j][half * 2], acc[i][j][half * 2 + 1]);
                if (MODE == 0) {
                    const int b    = r >> 11;
                    const int tt   = r & (T_ - 1);
                    const int part = c0 >> 10;
                    const int idx  = c0 & 1023;
                    const int h    = idx >> 6;
                    const int d    = idx & 63;
                    float* dst = (part == 0) ? g_q : (part == 1) ? g_k : g_v;
                    *(float2*)(dst + (((size_t)b * H_ + h) * T_ + tt) * HD_ + d) = v;
                } else {
                    *(float2*)(Cout + (size_t)r * N + c0) = v;
                }
            }
        }
    }
}

// ---------------------------------------------------------------------------
// RoPE (unchanged)
// ---------------------------------------------------------------------------
__global__ void rope_kernel()
{
    const int idx = blockIdx.x * blockDim.x + threadIdx.x;
    const int j  = idx & 31;
    const int t  = (idx >> 5) & (T_ - 1);
    const int bh = idx >> 16;

    const float f = exp2f(-(float)j * (13.287712379549449f / 32.0f));
    float s, c;
    sincosf((float)t * f, &s, &c);

    const size_t base = ((size_t)bh * T_ + t) * HD_;
    float a0 = g_q[base + j], b0 = g_q[base + j + 32];
    g_q[base + j]      = a0 * c - b0 * s;
    g_q[base + j + 32] = b0 * c + a0 * s;
    float a1 = g_k[base + j], b1 = g_k[base + j + 32];
    g_k[base + j]      = a1 * c - b1 * s;
    g_k[base + j + 32] = b1 * c + a1 * s;
}

// ---------------------------------------------------------------------------
// Flash attention (unchanged from R6/R7). Br=Bc=128, 256 threads, fp32.
// ---------------------------------------------------------------------------
#define BRF  128
#define QP   68
#define VP   132
#define PPCH 132
#define FLASH_SMEM ((2 * BRF * QP + HD_ * VP + BRF * PPCH) * (int)sizeof(float))

__global__ __launch_bounds__(256, 1)
void flash_kernel()
{
    extern __shared__ float sm[];
    float* Qs = sm;
    float* Ks = Qs + BRF * QP;
    float* Vt = Ks + BRF * QP;
    float* Ps = Vt + HD_ * VP;

    const int tid = threadIdx.x;
    const int tr  = tid >> 4;
    const int tc  = tid & 15;
    const int qtile = (int)gridDim.x - 1 - (int)blockIdx.x;
    const int bh    = blockIdx.y;

    const float* Qg = g_q + ((size_t)bh * T_ + (size_t)qtile * BRF) * HD_;
    const float* Kg = g_k + (size_t)bh * T_ * HD_;
    const float* Vg = g_v + (size_t)bh * T_ * HD_;

#pragma unroll
    for (int p = 0; p < 8; p++) {
        const int idx = tid + p * 256;
        const int r  = idx >> 4;
        const int c4 = (idx & 15) << 2;
        float4 q4 = *(const float4*)(Qg + r * HD_ + c4);
        *(float4*)&Qs[r * QP + c4] = q4;
    }

    float m_i[8], l_i[8], O[8][4];
#pragma unroll
    for (int i = 0; i < 8; i++) {
        m_i[i] = -INFINITY; l_i[i] = 0.0f;
#pragma unroll
        for (int j = 0; j < 4; j++) O[i][j] = 0.0f;
    }

    for (int kv = 0; kv <= qtile; kv++) {
        __syncthreads();
        const float* Kt = Kg + (size_t)kv * BRF * HD_;
        const float* Vv = Vg + (size_t)kv * BRF * HD_;
#pragma unroll
        for (int p = 0; p < 8; p++) {
            const int idx = tid + p * 256;
            const int r  = idx >> 4;
            const int c4 = (idx & 15) << 2;
            float4 k4 = *(const float4*)(Kt + r * HD_ + c4);
            *(float4*)&Ks[r * QP + c4] = k4;
            float4 v4 = *(const float4*)(Vv + r * HD_ + c4);
            Vt[(c4 + 0) * VP + r] = v4.x;
            Vt[(c4 + 1) * VP + r] = v4.y;
            Vt[(c4 + 2) * VP + r] = v4.z;
            Vt[(c4 + 3) * VP + r] = v4.w;
        }
        __syncthreads();

        float s[8][8];
#pragma unroll
        for (int i = 0; i < 8; i++)
#pragma unroll
            for (int j = 0; j < 8; j++) s[i][j] = 0.0f;

#pragma unroll
        for (int d0 = 0; d0 < HD_; d0 += 4) {
            float4 qv[8];
#pragma unroll
            for (int i = 0; i < 8; i++)
                qv[i] = *(const float4*)&Qs[(tr + 16 * i) * QP + d0];
#pragma unroll
            for (int j = 0; j < 8; j++) {
                const float4 kk = *(const float4*)&Ks[(tc + 16 * j) * QP + d0];
#pragma unroll
                for (int i = 0; i < 8; i++) {
                    s[i][j] = fmaf(qv[i].x, kk.x, s[i][j]);
                    s[i][j] = fmaf(qv[i].y, kk.y, s[i][j]);
                    s[i][j] = fmaf(qv[i].z, kk.z, s[i][j]);
                    s[i][j] = fmaf(qv[i].w, kk.w, s[i][j]);
                }
            }
        }

        const bool diag = (kv == qtile);
#pragma unroll
        for (int i = 0; i < 8; i++)
#pragma unroll
            for (int j = 0; j < 8; j++) {
                s[i][j] *= 0.125f;
                if (diag && (tc + 16 * j) > (tr + 16 * i)) s[i][j] = -1e30f;
            }

#pragma unroll
        for (int i = 0; i < 8; i++) {
            float rm = s[i][0];
#pragma unroll
            for (int j = 1; j < 8; j++) rm = fmaxf(rm, s[i][j]);
#pragma unroll
            for (int off = 8; off > 0; off >>= 1)
                rm = fmaxf(rm, __shfl_xor_sync(0xffffffffu, rm, off, 16));
            const float mnew  = fmaxf(m_i[i], rm);
            const float alpha = __expf(m_i[i] - mnew);
            m_i[i] = mnew;
            float rs = 0.0f;
#pragma unroll
            for (int j = 0; j < 8; j++) {
                const float p = __expf(s[i][j] - mnew);
                s[i][j] = p;
                rs += p;
            }
#pragma unroll
            for (int off = 8; off > 0; off >>= 1)
                rs += __shfl_xor_sync(0xffffffffu, rs, off, 16);
            l_i[i] = l_i[i] * alpha + rs;
#pragma unroll
            for (int j = 0; j < 4; j++) O[i][j] *= alpha;
#pragma unroll
            for (int j = 0; j < 8; j++)
                Ps[(tr + 16 * i) * PPCH + (tc + 16 * j)] = s[i][j];
        }
        __syncthreads();

#pragma unroll 4
        for (int c0 = 0; c0 < BRF; c0 += 4) {
            float4 pv[8];
#pragma unroll
            for (int i = 0; i < 8; i++)
                pv[i] = *(const float4*)&Ps[(tr + 16 * i) * PPCH + c0];
#pragma unroll
            for (int j = 0; j < 4; j++) {
                const float4 vv = *(const float4*)&Vt[(tc + 16 * j) * VP + c0];
#pragma unroll
                for (int i = 0; i < 8; i++) {
                    O[i][j] = fmaf(pv[i].x, vv.x, O[i][j]);
                    O[i][j] = fmaf(pv[i].y, vv.y, O[i][j]);
                    O[i][j] = fmaf(pv[i].z, vv.z, O[i][j]);
                    O[i][j] = fmaf(pv[i].w, vv.w, O[i][j]);
                }
            }
        }
    }

    const int b = bh >> 4;
    const int h = bh & 15;
#pragma unroll
    for (int i = 0; i < 8; i++) {
        const int trow = qtile * BRF + tr + 16 * i;
        const float inv_l = 1.0f / l_i[i];
#pragma unroll
        for (int j = 0; j < 4; j++) {
            g_att[(((size_t)b * T_ + trow) * H_ + h) * HD_ + tc + 16 * j] = O[i][j] * inv_l;
        }
    }
}

// ---------------------------------------------------------------------------
extern "C" void kernel_launch(void* const* d_in, const int* in_sizes, int n_in,
                              void* d_out, int out_size)
{
    const float* x     = (const float*)d_in[0];
    // d_in[1] = mask (causal, static — ignored)
    const float* w_qkv = (const float*)d_in[2];
    const float* w_out = (const float*)d_in[3];
    float* out = (float*)d_out;

    cudaFuncSetAttribute(flash_kernel,
                         cudaFuncAttributeMaxDynamicSharedMemorySize, FLASH_SMEM);
    cudaFuncSetAttribute(bgemm<0>,
                         cudaFuncAttributeMaxDynamicSharedMemorySize, BGEMM_SMEM);
    cudaFuncSetAttribute(bgemm<1>,
                         cudaFuncAttributeMaxDynamicSharedMemorySize, BGEMM_SMEM);

    __nv_bfloat16 *xh, *xl, *wqh, *wql, *woh, *wol, *ath, *atl;
    cudaGetSymbolAddress((void**)&xh,  g_xh);   cudaGetSymbolAddress((void**)&xl,  g_xl);
    cudaGetSymbolAddress((void**)&wqh, g_wqkvTh); cudaGetSymbolAddress((void**)&wql, g_wqkvTl);
    cudaGetSymbolAddress((void**)&woh, g_woutTh); cudaGetSymbolAddress((void**)&wol, g_woutTl);
    cudaGetSymbolAddress((void**)&ath, g_atth); cudaGetSymbolAddress((void**)&atl, g_attl);
    float* att; cudaGetSymbolAddress((void**)&att, g_att);

    // 0) split x; split+transpose weights
    split4_kernel<<<(M_*D_/4 + 255)/256, 256>>>((const float4*)x,
        (__nv_bfloat162*)xh, (__nv_bfloat162*)xl, M_*D_/4);
    splitT_kernel<<<dim3(NQKV_/32, D_/32), dim3(32, 8)>>>(w_qkv, wqh, wql, D_, NQKV_);
    splitT_kernel<<<dim3(D_/32,  D_/32), dim3(32, 8)>>>(w_out, woh, wol, D_, D_);

    // 1) qkv = x @ w_qkv  (bf16 split tensor GEMM) -> scatter q/k/v
    bgemm<0><<<dim3(NQKV_/128, M_/128), 256, BGEMM_SMEM>>>(xh, xl, wqh, wql,
                                                           nullptr, NQKV_, K_);
    // 2) RoPE
    rope_kernel<<<(B_ * H_ * T_ * 32) / 256, 256>>>();

    // 3) causal flash attention -> g_att (fp32)
    flash_kernel<<<dim3(T_ / BRF, B_ * H_), 256, FLASH_SMEM>>>();

    // 4) split att, then out = att @ w_out (bf16 split tensor GEMM)
    split4_kernel<<<(M_*D_/4 + 255)/256, 256>>>((const float4*)att,
        (__nv_bfloat162*)ath, (__nv_bfloat162*)atl, M_*D_/4);
    bgemm<1><<<dim3(D_/128, M_/128), 256, BGEMM_SMEM>>>(ath, atl, woh, wol,
                                                        out, D_, K_);
}

// round 9
// speedup vs baseline: 2.8113x; 1.6107x over previous
#include <cuda_runtime.h>
#include <cuda_bf16.h>
#include <math.h>
#include <stdint.h>

// Problem constants
#define B_   2
#define H_   16
#define T_   2048
#define D_   1024
#define HD_  64
#define M_   (B_*T_)      // 4096 rows
#define NQKV_ (3*D_)      // 3072
#define K_   1024

// Scratch (device globals: allocation-free rule)
__device__ float g_q[B_*H_*T_*HD_];   // fp32 pre-rope
__device__ float g_k[B_*H_*T_*HD_];
__device__ float g_v[B_*H_*T_*HD_];

// bf16 split operands
__device__ __align__(16) __nv_bfloat16 g_xh[M_*D_],    g_xl[M_*D_];
__device__ __align__(16) __nv_bfloat16 g_wqkvTh[NQKV_*D_], g_wqkvTl[NQKV_*D_];
__device__ __align__(16) __nv_bfloat16 g_woutTh[D_*D_],   g_woutTl[D_*D_];
__device__ __align__(16) __nv_bfloat16 g_atth[M_*D_],  g_attl[M_*D_];
__device__ __align__(16) __nv_bfloat16 g_qh[B_*H_*T_*HD_], g_ql[B_*H_*T_*HD_];  // [bh][t][d]
__device__ __align__(16) __nv_bfloat16 g_kh[B_*H_*T_*HD_], g_kl[B_*H_*T_*HD_];  // [bh][t][d]
__device__ __align__(16) __nv_bfloat16 g_vth[B_*H_*T_*HD_], g_vtl[B_*H_*T_*HD_]; // [bh][d][t]

__device__ __forceinline__ uint32_t smem_u32(const void* p) {
    uint32_t a;
    asm("{ .reg .u64 t; cvta.to.shared.u64 t, %1; cvt.u32.u64 %0, t; }" : "=r"(a) : "l"(p));
    return a;
}
__device__ __forceinline__ void cp_async16(uint32_t dst, const void* src) {
    asm volatile("cp.async.cg.shared.global [%0], [%1], 16;" :: "r"(dst), "l"(src));
}
__device__ __forceinline__ void cp_commit() { asm volatile("cp.async.commit_group;" ::: "memory"); }
__device__ __forceinline__ void cp_wait0()  { asm volatile("cp.async.wait_group 0;" ::: "memory"); }
__device__ __forceinline__ uint32_t lds32(uint32_t a) {
    uint32_t v;
    asm volatile("ld.shared.b32 %0, [%1];" : "=r"(v) : "r"(a));
    return v;
}
__device__ __forceinline__ void mma_bf16(float c[4], const uint32_t a[4], const uint32_t b[2]) {
    asm volatile(
        "mma.sync.aligned.m16n8k16.row.col.f32.bf16.bf16.f32 "
        "{%0,%1,%2,%3}, {%4,%5,%6,%7}, {%8,%9}, {%0,%1,%2,%3};"
        : "+f"(c[0]), "+f"(c[1]), "+f"(c[2]), "+f"(c[3])
        : "r"(a[0]), "r"(a[1]), "r"(a[2]), "r"(a[3]), "r"(b[0]), "r"(b[1]));
}
__device__ __forceinline__ void split1(float v, __nv_bfloat16& h, __nv_bfloat16& l) {
    h = __float2bfloat16(v);
    l = __float2bfloat16(v - __bfloat162float(h));
}
// pack (x,y) -> bf16x2 hi word + lo word
__device__ __forceinline__ void split2(float x, float y, uint32_t& h, uint32_t& l) {
    __nv_bfloat16 hx, lx, hy, ly;
    split1(x, hx, lx); split1(y, hy, ly);
    __nv_bfloat162 hv(hx, hy), lv(lx, ly);
    h = *(uint32_t*)&hv; l = *(uint32_t*)&lv;
}

// ---------------------------------------------------------------------------
// split4: fp32[n] -> bf16 hi[n], lo[n]
// ---------------------------------------------------------------------------
__global__ void split4_kernel(const float4* __restrict__ src,
                              __nv_bfloat162* __restrict__ h,
                              __nv_bfloat162* __restrict__ l, int n4)
{
    const int i = blockIdx.x * blockDim.x + threadIdx.x;
    if (i >= n4) return;
    const float4 v = src[i];
    __nv_bfloat16 hx, lx, hy, ly, hz, lz, hw, lw;
    split1(v.x, hx, lx); split1(v.y, hy, ly);
    split1(v.z, hz, lz); split1(v.w, hw, lw);
    h[2*i]   = __nv_bfloat162(hx, hy);
    h[2*i+1] = __nv_bfloat162(hz, hw);
    l[2*i]   = __nv_bfloat162(lx, ly);
    l[2*i+1] = __nv_bfloat162(lz, lw);
}

// ---------------------------------------------------------------------------
// splitT: fp32 src[R][C] -> bf16 hT[C][R], lT[C][R]
// ---------------------------------------------------------------------------
__global__ void splitT_kernel(const float* __restrict__ src,
                              __nv_bfloat16* __restrict__ hT,
                              __nv_bfloat16* __restrict__ lT, int R, int C)
{
    __shared__ float tile[32][33];
    const int bx = blockIdx.x * 32, by = blockIdx.y * 32;
    const int tx = threadIdx.x, ty = threadIdx.y;
#pragma unroll
    for (int i = 0; i < 32; i += 8)
        tile[ty + i][tx] = src[(size_t)(by + ty + i) * C + bx + tx];
    __syncthreads();
#pragma unroll
    for (int i = 0; i < 32; i += 8) {
        const float v = tile[tx][ty + i];
        __nv_bfloat16 h, l;
        split1(v, h, l);
        const size_t o = (size_t)(bx + ty + i) * R + by + tx;
        hT[o] = h; lT[o] = l;
    }
}

// ---------------------------------------------------------------------------
// vsplitT: per-bh transpose+split g_v [bh][t][d] -> g_vth/l [bh][d][t]
// grid: (T/32, HD/32, BH), block (32,8)
// ---------------------------------------------------------------------------
__global__ void vsplitT_kernel()
{
    __shared__ float tile[32][33];
    const int bt = blockIdx.x * 32, bd = blockIdx.y * 32, bh = blockIdx.z;
    const int tx = threadIdx.x, ty = threadIdx.y;
    const float* src = g_v + (size_t)bh * T_ * HD_;
    __nv_bfloat16* dh = g_vth + (size_t)bh * HD_ * T_;
    __nv_bfloat16* dl = g_vtl + (size_t)bh * HD_ * T_;
#pragma unroll
    for (int i = 0; i < 32; i += 8)
        tile[ty + i][tx] = src[(size_t)(bt + ty + i) * HD_ + bd + tx];
    __syncthreads();
#pragma unroll
    for (int i = 0; i < 32; i += 8) {
        const float v = tile[tx][ty + i];
        __nv_bfloat16 h, l;
        split1(v, h, l);
        const size_t o = (size_t)(bd + ty + i) * T_ + bt + tx;
        dh[o] = h; dl[o] = l;
    }
}

// ---------------------------------------------------------------------------
// bf16 split-GEMM (unchanged from R8)
// ---------------------------------------------------------------------------
#define PB    40
#define MATB  (128 * PB * 2)
#define BUFB  (4 * MATB)
#define BGEMM_SMEM (2 * BUFB)

template<int MODE>
__global__ __launch_bounds__(256, 2)
void bgemm(const __nv_bfloat16* __restrict__ Ah, const __nv_bfloat16* __restrict__ Al,
           const __nv_bfloat16* __restrict__ Bh, const __nv_bfloat16* __restrict__ Bl,
           float* __restrict__ Cout, int N, int K)
{
    extern __shared__ char smc[];
    const uint32_t sb = smem_u32(smc);

    const int tid  = threadIdx.x;
    const int wid  = tid >> 5;
    const int lane = tid & 31;
    const int g    = lane >> 2;
    const int tig  = lane & 3;
    const int warp_m = wid >> 2;
    const int warp_n = wid & 3;
    const int bm = blockIdx.y;
    const int bn = blockIdx.x;

    const char* gsrc[4] = {
        (const char*)(Ah + (size_t)bm * 128 * K),
        (const char*)(Al + (size_t)bm * 128 * K),
        (const char*)(Bh + (size_t)bn * 128 * K),
        (const char*)(Bl + (size_t)bn * 128 * K)
    };
    const size_t grs = (size_t)K * 2;

    float acc[4][4][4];
#pragma unroll
    for (int i = 0; i < 4; i++)
#pragma unroll
        for (int j = 0; j < 4; j++)
#pragma unroll
            for (int e = 0; e < 4; e++) acc[i][j][e] = 0.0f;

    const int NT = K / 32;

#pragma unroll
    for (int p = 0; p < 8; p++) {
        const int c   = tid + p * 256;
        const int mat = c >> 9;
        const int r   = (c >> 2) & 127;
        const int q   = (c & 3) * 16;
        cp_async16(sb + mat * MATB + r * (PB * 2) + q,
                   gsrc[mat] + (size_t)r * grs + q);
    }
    cp_commit();
    cp_wait0();
    __syncthreads();

    for (int t = 0; t < NT; t++) {
        const int buf = t & 1;

        if (t + 1 < NT) {
            const uint32_t db = sb + (buf ^ 1) * BUFB;
            const size_t kb = (size_t)(t + 1) * 64;
#pragma unroll
            for (int p = 0; p < 8; p++) {
                const int c   = tid + p * 256;
                const int mat = c >> 9;
                const int r   = (c >> 2) & 127;
                const int q   = (c & 3) * 16;
                cp_async16(db + mat * MATB + r * (PB * 2) + q,
                           gsrc[mat] + (size_t)r * grs + kb + q);
            }
            cp_commit();
        }

        const uint32_t base = sb + buf * BUFB;
#pragma unroll
        for (int ks = 0; ks < 2; ks++) {
            const uint32_t ko = ks * 32 + tig * 4;

            uint32_t ah[4][4], al[4][4], bh[4][2], bl[4][2];
#pragma unroll
            for (int i = 0; i < 4; i++) {
                const uint32_t ab = base + (warp_m * 64 + i * 16 + g) * (PB * 2) + ko;
                ah[i][0] = lds32(ab);       ah[i][1] = lds32(ab + 8 * PB * 2);
                ah[i][2] = lds32(ab + 16);  ah[i][3] = lds32(ab + 8 * PB * 2 + 16);
            }
#pragma unroll
            for (int j = 0; j < 4; j++) {
                const uint32_t bb = base + 2 * MATB + (warp_n * 32 + j * 8 + g) * (PB * 2) + ko;
                bh[j][0] = lds32(bb);       bh[j][1] = lds32(bb + 16);
            }
#pragma unroll
            for (int i = 0; i < 4; i++)
#pragma unroll
                for (int j = 0; j < 4; j++)
                    mma_bf16(acc[i][j], ah[i], bh[j]);

#pragma unroll
            for (int i = 0; i < 4; i++) {
                const uint32_t ab = base + MATB + (warp_m * 64 + i * 16 + g) * (PB * 2) + ko;
                al[i][0] = lds32(ab);       al[i][1] = lds32(ab + 8 * PB * 2);
                al[i][2] = lds32(ab + 16);  al[i][3] = lds32(ab + 8 * PB * 2 + 16);
            }
#pragma unroll
            for (int i = 0; i < 4; i++)
#pragma unroll
                for (int j = 0; j < 4; j++)
                    mma_bf16(acc[i][j], al[i], bh[j]);

#pragma unroll
            for (int j = 0; j < 4; j++) {
                const uint32_t bb = base + 3 * MATB + (warp_n * 32 + j * 8 + g) * (PB * 2) + ko;
                bl[j][0] = lds32(bb);       bl[j][1] = lds32(bb + 16);
            }
#pragma unroll
            for (int i = 0; i < 4; i++)
#pragma unroll
                for (int j = 0; j < 4; j++)
                    mma_bf16(acc[i][j], ah[i], bl[j]);
        }

        if (t + 1 < NT) cp_wait0();
        __syncthreads();
    }

#pragma unroll
    for (int i = 0; i < 4; i++) {
        const int r0 = bm * 128 + warp_m * 64 + i * 16 + g;
#pragma unroll
        for (int j = 0; j < 4; j++) {
            const int c0 = bn * 128 + warp_n * 32 + j * 8 + tig * 2;
#pragma unroll
            for (int half = 0; half < 2; half++) {
                const int r = r0 + half * 8;
                const float2 v = make_float2(acc[i][j][half * 2], acc[i][j][half * 2 + 1]);
                if (MODE == 0) {
                    const int b    = r >> 11;
                    const int tt   = r & (T_ - 1);
                    const int part = c0 >> 10;
                    const int idx  = c0 & 1023;
                    const int h    = idx >> 6;
                    const int d    = idx & 63;
                    float* dst = (part == 0) ? g_q : (part == 1) ? g_k : g_v;
                    *(float2*)(dst + (((size_t)b * H_ + h) * T_ + tt) * HD_ + d) = v;
                } else {
                    *(float2*)(Cout + (size_t)r * N + c0) = v;
                }
            }
        }
    }
}

// ---------------------------------------------------------------------------
// RoPE: read fp32 g_q/g_k, write split bf16 g_qh/l, g_kh/l ([bh][t][d])
// ---------------------------------------------------------------------------
__global__ void rope_kernel()
{
    const int idx = blockIdx.x * blockDim.x + threadIdx.x;
    const int j  = idx & 31;
    const int t  = (idx >> 5) & (T_ - 1);
    const int bh = idx >> 16;

    const float f = exp2f(-(float)j * (13.287712379549449f / 32.0f));
    float s, c;
    sincosf((float)t * f, &s, &c);

    const size_t base = ((size_t)bh * T_ + t) * HD_;
    float a0 = g_q[base + j], b0 = g_q[base + j + 32];
    float a1 = g_k[base + j], b1 = g_k[base + j + 32];
    const float q0 = a0 * c - b0 * s, q1 = b0 * c + a0 * s;
    const float k0 = a1 * c - b1 * s, k1 = b1 * c + a1 * s;
    __nv_bfloat16 h, l;
    split1(q0, h, l); g_qh[base + j] = h;      g_ql[base + j] = l;
    split1(q1, h, l); g_qh[base + j + 32] = h; g_ql[base + j + 32] = l;
    split1(k0, h, l); g_kh[base + j] = h;      g_kl[base + j] = l;
    split1(k1, h, l); g_kh[base + j + 32] = h; g_kl[base + j + 32] = l;
}

// ---------------------------------------------------------------------------
// Tensor-core flash attention, causal, split bf16 (3-mma), fp32 softmax.
// CTA: 128 q-rows x bh. 8 warps; warp w owns rows 16w..16w+15.
// S: m16n8k16, Q A-frags in regs, K B-frags from smem (pitch 72 bf16).
// P: S accumulators -> A-frags directly in registers (hi/lo split).
// PV: V^T B-frags from smem (pitch 136 bf16). O fp32 accum in regs.
// ---------------------------------------------------------------------------
#define KPIT 72     // K/Q smem pitch (bf16)
#define VPIT 136    // Vt smem pitch (bf16)
#define SM_KH 0
#define SM_KL (128 * KPIT)
#define SM_VH (2 * 128 * KPIT)
#define SM_VL (2 * 128 * KPIT + 64 * VPIT)
#define FLASH_SMEM ((2 * 128 * KPIT + 2 * 64 * VPIT) * 2)   // bytes = 71680

__global__ __launch_bounds__(256, 1)
void flash_tc()
{
    extern __shared__ __nv_bfloat16 smb[];
    __nv_bfloat16* Karr[2] = { smb + SM_KH, smb + SM_KL };
    __nv_bfloat16* Varr[2] = { smb + SM_VH, smb + SM_VL };
    const uint32_t skh = smem_u32(smb + SM_KH);
    const uint32_t skl = smem_u32(smb + SM_KL);
    const uint32_t svh = smem_u32(smb + SM_VH);
    const uint32_t svl = smem_u32(smb + SM_VL);

    const int tid  = threadIdx.x;
    const int wid  = tid >> 5;
    const int lane = tid & 31;
    const int g    = lane >> 2;
    const int tig  = lane & 3;
    const int qtile = (int)gridDim.x - 1 - (int)blockIdx.x;
    const int bh    = blockIdx.y;

    const size_t qkbase = ((size_t)bh * T_ + (size_t)qtile * 128) * HD_;
    const size_t kvrow0 = (size_t)bh * T_ * HD_;
    const size_t vtbase = (size_t)bh * HD_ * T_;

    // ---- stage Q into K smem area, extract A-fragments, release ----
    {
        const __nv_bfloat16* qsrc[2] = { g_qh + qkbase, g_ql + qkbase };
#pragma unroll
        for (int p = 0; p < 8; p++) {
            const int c   = tid + p * 256;
            const int mat = c >> 10;
            const int rem = c & 1023;
            const int r   = rem >> 3;
            const int c8  = (rem & 7) * 8;
            *(uint4*)(Karr[mat] + r * KPIT + c8) =
                *(const uint4*)(qsrc[mat] + r * HD_ + c8);
        }
    }
    __syncthreads();

    uint32_t qfh[4][4], qfl[4][4];
#pragma unroll
    for (int kb = 0; kb < 4; kb++) {
        const uint32_t off = (16 * wid + g) * (KPIT * 2) + kb * 32 + tig * 4;
        qfh[kb][0] = lds32(skh + off);
        qfh[kb][1] = lds32(skh + off + 8 * (KPIT * 2));
        qfh[kb][2] = lds32(skh + off + 16);
        qfh[kb][3] = lds32(skh + off + 8 * (KPIT * 2) + 16);
        qfl[kb][0] = lds32(skl + off);
        qfl[kb][1] = lds32(skl + off + 8 * (KPIT * 2));
        qfl[kb][2] = lds32(skl + off + 16);
        qfl[kb][3] = lds32(skl + off + 8 * (KPIT * 2) + 16);
    }

    float o[8][4];
#pragma unroll
    for (int nt = 0; nt < 8; nt++)
#pragma unroll
        for (int e = 0; e < 4; e++) o[nt][e] = 0.0f;
    float m0 = -INFINITY, m1 = -INFINITY, l0 = 0.0f, l1 = 0.0f;

    for (int kv = 0; kv <= qtile; kv++) {
        __syncthreads();   // smem free (Q frags extracted / prev tile done)
        {
            const __nv_bfloat16* ksrc[2] = { g_kh + kvrow0 + (size_t)kv * 128 * HD_,
                                             g_kl + kvrow0 + (size_t)kv * 128 * HD_ };
            const __nv_bfloat16* vsrc[2] = { g_vth + vtbase + (size_t)kv * 128,
                                             g_vtl + vtbase + (size_t)kv * 128 };
#pragma unroll
            for (int p = 0; p < 8; p++) {
                const int c   = tid + p * 256;
                const int mat = c >> 10;
                const int rem = c & 1023;
                const int r   = rem >> 3;
                const int c8  = (rem & 7) * 8;
                *(uint4*)(Karr[mat] + r * KPIT + c8) =
                    *(const uint4*)(ksrc[mat] + r * HD_ + c8);
            }
#pragma unroll
            for (int p = 0; p < 8; p++) {
                const int c   = tid + p * 256;
                const int mat = c >> 10;
                const int rem = c & 1023;
                const int d   = rem >> 4;
                const int c8  = (rem & 15) * 8;
                *(uint4*)(Varr[mat] + d * VPIT + c8) =
                    *(const uint4*)(vsrc[mat] + (size_t)d * T_ + c8);
            }
        }
        __syncthreads();

        // ---- S = Q K^T (split 3-mma) ----
        float cS[16][4];
#pragma unroll
        for (int j = 0; j < 16; j++)
#pragma unroll
            for (int e = 0; e < 4; e++) cS[j][e] = 0.0f;

#pragma unroll
        for (int kb = 0; kb < 4; kb++) {
#pragma unroll
            for (int j = 0; j < 16; j++) {
                const uint32_t off = (j * 8 + g) * (KPIT * 2) + kb * 32 + tig * 4;
                uint32_t bh_[2], bl_[2];
                bh_[0] = lds32(skh + off);  bh_[1] = lds32(skh + off + 16);
                mma_bf16(cS[j], qfh[kb], bh_);
                mma_bf16(cS[j], qfl[kb], bh_);
                bl_[0] = lds32(skl + off);  bl_[1] = lds32(skl + off + 16);
                mma_bf16(cS[j], qfh[kb], bl_);
            }
        }

        // ---- scale + causal mask ----
        const bool diag = (kv == qtile);
        const int row0 = 16 * wid + g;
#pragma unroll
        for (int j = 0; j < 16; j++) {
            const int col0 = j * 8 + 2 * tig;
            cS[j][0] *= 0.125f; cS[j][1] *= 0.125f;
            cS[j][2] *= 0.125f; cS[j][3] *= 0.125f;
            if (diag) {
                if (col0     > row0)     cS[j][0] = -1e30f;
                if (col0 + 1 > row0)     cS[j][1] = -1e30f;
                if (col0     > row0 + 8) cS[j][2] = -1e30f;
                if (col0 + 1 > row0 + 8) cS[j][3] = -1e30f;
            }
        }

        // ---- online softmax (rows g, g+8; reduce over 4 lanes tig) ----
        float mx0 = -INFINITY, mx1 = -INFINITY;
#pragma unroll
        for (int j = 0; j < 16; j++) {
            mx0 = fmaxf(mx0, fmaxf(cS[j][0], cS[j][1]));
            mx1 = fmaxf(mx1, fmaxf(cS[j][2], cS[j][3]));
        }
        mx0 = fmaxf(mx0, __shfl_xor_sync(0xffffffffu, mx0, 1));
        mx0 = fmaxf(mx0, __shfl_xor_sync(0xffffffffu, mx0, 2));
        mx1 = fmaxf(mx1, __shfl_xor_sync(0xffffffffu, mx1, 1));
        mx1 = fmaxf(mx1, __shfl_xor_sync(0xffffffffu, mx1, 2));

        const float nm0 = fmaxf(m0, mx0), nm1 = fmaxf(m1, mx1);
        const float al0 = __expf(m0 - nm0), al1 = __expf(m1 - nm1);
        m0 = nm0; m1 = nm1;

        float rs0 = 0.0f, rs1 = 0.0f;
#pragma unroll
        for (int j = 0; j < 16; j++) {
            cS[j][0] = __expf(cS[j][0] - m0);
            cS[j][1] = __expf(cS[j][1] - m0);
            cS[j][2] = __expf(cS[j][2] - m1);
            cS[j][3] = __expf(cS[j][3] - m1);
            rs0 += cS[j][0] + cS[j][1];
            rs1 += cS[j][2] + cS[j][3];
        }
        rs0 += __shfl_xor_sync(0xffffffffu, rs0, 1);
        rs0 += __shfl_xor_sync(0xffffffffu, rs0, 2);
        rs1 += __shfl_xor_sync(0xffffffffu, rs1, 1);
        rs1 += __shfl_xor_sync(0xffffffffu, rs1, 2);
        l0 = l0 * al0 + rs0;
        l1 = l1 * al1 + rs1;

#pragma unroll
        for (int nt = 0; nt < 8; nt++) {
            o[nt][0] *= al0; o[nt][1] *= al0;
            o[nt][2] *= al1; o[nt][3] *= al1;
        }

        // ---- PV: pack P frags per k-block, mma against Vt ----
#pragma unroll
        for (int kb2 = 0; kb2 < 8; kb2++) {
            uint32_t aph[4], apl[4];
            split2(cS[2*kb2][0],   cS[2*kb2][1],   aph[0], apl[0]);
            split2(cS[2*kb2][2],   cS[2*kb2][3],   aph[1], apl[1]);
            split2(cS[2*kb2+1][0], cS[2*kb2+1][1], aph[2], apl[2]);
            split2(cS[2*kb2+1][2], cS[2*kb2+1][3], aph[3], apl[3]);
#pragma unroll
            for (int nt = 0; nt < 8; nt++) {
                const uint32_t off = (nt * 8 + g) * (VPIT * 2) + kb2 * 32 + tig * 4;
                uint32_t vh_[2], vl_[2];
                vh_[0] = lds32(svh + off);  vh_[1] = lds32(svh + off + 16);
                mma_bf16(o[nt], aph, vh_);
                mma_bf16(o[nt], apl, vh_);
                vl_[0] = lds32(svl + off);  vl_[1] = lds32(svl + off + 16);
                mma_bf16(o[nt], aph, vl_);
            }
        }
    }

    // ---- epilogue: write split att directly ----
    const int b = bh >> 4;
    const int h = bh & 15;
    const int t0 = qtile * 128 + 16 * wid + g;
    const float inv0 = 1.0f / l0, inv1 = 1.0f / l1;
#pragma unroll
    for (int nt = 0; nt < 8; nt++) {
        const int d = nt * 8 + 2 * tig;
        uint32_t ph, pl;
        split2(o[nt][0] * inv0, o[nt][1] * inv0, ph, pl);
        const size_t off0 = ((size_t)b * T_ + t0) * D_ + h * HD_ + d;
        *(uint32_t*)(g_atth + off0) = ph;
        *(uint32_t*)(g_attl + off0) = pl;
        split2(o[nt][2] * inv1, o[nt][3] * inv1, ph, pl);
        const size_t off1 = ((size_t)b * T_ + t0 + 8) * D_ + h * HD_ + d;
        *(uint32_t*)(g_atth + off1) = ph;
        *(uint32_t*)(g_attl + off1) = pl;
    }
}

// ---------------------------------------------------------------------------
extern "C" void kernel_launch(void* const* d_in, const int* in_sizes, int n_in,
                              void* d_out, int out_size)
{
    const float* x     = (const float*)d_in[0];
    // d_in[1] = mask (causal, static — ignored)
    const float* w_qkv = (const float*)d_in[2];
    const float* w_out = (const float*)d_in[3];
    float* out = (float*)d_out;

    cudaFuncSetAttribute(bgemm<0>, cudaFuncAttributeMaxDynamicSharedMemorySize, BGEMM_SMEM);
    cudaFuncSetAttribute(bgemm<1>, cudaFuncAttributeMaxDynamicSharedMemorySize, BGEMM_SMEM);
    cudaFuncSetAttribute(flash_tc, cudaFuncAttributeMaxDynamicSharedMemorySize, FLASH_SMEM);

    __nv_bfloat16 *xh, *xl, *wqh, *wql, *woh, *wol, *ath, *atl;
    cudaGetSymbolAddress((void**)&xh,  g_xh);     cudaGetSymbolAddress((void**)&xl,  g_xl);
    cudaGetSymbolAddress((void**)&wqh, g_wqkvTh); cudaGetSymbolAddress((void**)&wql, g_wqkvTl);
    cudaGetSymbolAddress((void**)&woh, g_woutTh); cudaGetSymbolAddress((void**)&wol, g_woutTl);
    cudaGetSymbolAddress((void**)&ath, g_atth);   cudaGetSymbolAddress((void**)&atl, g_attl);

    // 0) split x; split+transpose weights
    split4_kernel<<<(M_*D_/4 + 255)/256, 256>>>((const float4*)x,
        (__nv_bfloat162*)xh, (__nv_bfloat162*)xl, M_*D_/4);
    splitT_kernel<<<dim3(NQKV_/32, D_/32), dim3(32, 8)>>>(w_qkv, wqh, wql, D_, NQKV_);
    splitT_kernel<<<dim3(D_/32,  D_/32), dim3(32, 8)>>>(w_out, woh, wol, D_, D_);

    // 1) qkv = x @ w_qkv (tensor) -> g_q/g_k/g_v fp32
    bgemm<0><<<dim3(NQKV_/128, M_/128), 256, BGEMM_SMEM>>>(xh, xl, wqh, wql,
                                                           nullptr, NQKV_, K_);
    // 2) RoPE -> split bf16 q/k;  V -> transpose+split
    rope_kernel<<<(B_ * H_ * T_ * 32) / 256, 256>>>();
    vsplitT_kernel<<<dim3(T_/32, HD_/32, B_*H_), dim3(32, 8)>>>();

    // 3) tensor-core causal flash attention -> split att directly
    flash_tc<<<dim3(T_ / 128, B_ * H_), 256, FLASH_SMEM>>>();

    // 4) out = att @ w_out (tensor)
    bgemm<1><<<dim3(D_/128, M_/128), 256, BGEMM_SMEM>>>(ath, atl, woh, wol,
                                                        out, D_, K_);
}

// round 10
// speedup vs baseline: 3.0071x; 1.0696x over previous
#include <cuda_runtime.h>
#include <cuda_bf16.h>
#include <math.h>
#include <stdint.h>

// Problem constants
#define B_   2
#define H_   16
#define T_   2048
#define D_   1024
#define HD_  64
#define M_   (B_*T_)      // 4096 rows
#define NQKV_ (3*D_)      // 3072
#define K_   1024

// Scratch (device globals: allocation-free rule)
__device__ float g_q[B_*H_*T_*HD_];   // fp32 pre-rope
__device__ float g_k[B_*H_*T_*HD_];
__device__ float g_v[B_*H_*T_*HD_];

// bf16 split operands
__device__ __align__(16) __nv_bfloat16 g_xh[M_*D_],    g_xl[M_*D_];
__device__ __align__(16) __nv_bfloat16 g_wqkvTh[NQKV_*D_], g_wqkvTl[NQKV_*D_];
__device__ __align__(16) __nv_bfloat16 g_woutTh[D_*D_],   g_woutTl[D_*D_];
__device__ __align__(16) __nv_bfloat16 g_atth[M_*D_],  g_attl[M_*D_];
__device__ __align__(16) __nv_bfloat16 g_qh[B_*H_*T_*HD_], g_ql[B_*H_*T_*HD_];  // [bh][t][d]
__device__ __align__(16) __nv_bfloat16 g_kh[B_*H_*T_*HD_], g_kl[B_*H_*T_*HD_];  // [bh][t][d]
__device__ __align__(16) __nv_bfloat16 g_vth[B_*H_*T_*HD_], g_vtl[B_*H_*T_*HD_]; // [bh][d][t]

__device__ __forceinline__ uint32_t smem_u32(const void* p) {
    uint32_t a;
    asm("{ .reg .u64 t; cvta.to.shared.u64 t, %1; cvt.u32.u64 %0, t; }" : "=r"(a) : "l"(p));
    return a;
}
__device__ __forceinline__ void cp_async16(uint32_t dst, const void* src) {
    asm volatile("cp.async.cg.shared.global [%0], [%1], 16;" :: "r"(dst), "l"(src));
}
__device__ __forceinline__ void cp_commit() { asm volatile("cp.async.commit_group;" ::: "memory"); }
__device__ __forceinline__ void cp_wait0()  { asm volatile("cp.async.wait_group 0;" ::: "memory"); }
__device__ __forceinline__ void ldsm4(uint32_t r[4], uint32_t addr) {
    asm volatile("ldmatrix.sync.aligned.m8n8.x4.shared.b16 {%0,%1,%2,%3}, [%4];"
        : "=r"(r[0]), "=r"(r[1]), "=r"(r[2]), "=r"(r[3]) : "r"(addr));
}
__device__ __forceinline__ void mma_bf16(float c[4], const uint32_t a[4], const uint32_t b[2]) {
    asm volatile(
        "mma.sync.aligned.m16n8k16.row.col.f32.bf16.bf16.f32 "
        "{%0,%1,%2,%3}, {%4,%5,%6,%7}, {%8,%9}, {%0,%1,%2,%3};"
        : "+f"(c[0]), "+f"(c[1]), "+f"(c[2]), "+f"(c[3])
        : "r"(a[0]), "r"(a[1]), "r"(a[2]), "r"(a[3]), "r"(b[0]), "r"(b[1]));
}
__device__ __forceinline__ void split1(float v, __nv_bfloat16& h, __nv_bfloat16& l) {
    h = __float2bfloat16(v);
    l = __float2bfloat16(v - __bfloat162float(h));
}
__device__ __forceinline__ void split2(float x, float y, uint32_t& h, uint32_t& l) {
    __nv_bfloat16 hx, lx, hy, ly;
    split1(x, hx, lx); split1(y, hy, ly);
    __nv_bfloat162 hv(hx, hy), lv(lx, ly);
    h = *(uint32_t*)&hv; l = *(uint32_t*)&lv;
}

// ---------------------------------------------------------------------------
// split4 / splitT / vsplitT feeders (unchanged from R9)
// ---------------------------------------------------------------------------
__global__ void split4_kernel(const float4* __restrict__ src,
                              __nv_bfloat162* __restrict__ h,
                              __nv_bfloat162* __restrict__ l, int n4)
{
    const int i = blockIdx.x * blockDim.x + threadIdx.x;
    if (i >= n4) return;
    const float4 v = src[i];
    __nv_bfloat16 hx, lx, hy, ly, hz, lz, hw, lw;
    split1(v.x, hx, lx); split1(v.y, hy, ly);
    split1(v.z, hz, lz); split1(v.w, hw, lw);
    h[2*i]   = __nv_bfloat162(hx, hy);
    h[2*i+1] = __nv_bfloat162(hz, hw);
    l[2*i]   = __nv_bfloat162(lx, ly);
    l[2*i+1] = __nv_bfloat162(lz, lw);
}

__global__ void splitT_kernel(const float* __restrict__ src,
                              __nv_bfloat16* __restrict__ hT,
                              __nv_bfloat16* __restrict__ lT, int R, int C)
{
    __shared__ float tile[32][33];
    const int bx = blockIdx.x * 32, by = blockIdx.y * 32;
    const int tx = threadIdx.x, ty = threadIdx.y;
#pragma unroll
    for (int i = 0; i < 32; i += 8)
        tile[ty + i][tx] = src[(size_t)(by + ty + i) * C + bx + tx];
    __syncthreads();
#pragma unroll
    for (int i = 0; i < 32; i += 8) {
        const float v = tile[tx][ty + i];
        __nv_bfloat16 h, l;
        split1(v, h, l);
        const size_t o = (size_t)(bx + ty + i) * R + by + tx;
        hT[o] = h; lT[o] = l;
    }
}

__global__ void vsplitT_kernel()
{
    __shared__ float tile[32][33];
    const int bt = blockIdx.x * 32, bd = blockIdx.y * 32, bh = blockIdx.z;
    const int tx = threadIdx.x, ty = threadIdx.y;
    const float* src = g_v + (size_t)bh * T_ * HD_;
    __nv_bfloat16* dh = g_vth + (size_t)bh * HD_ * T_;
    __nv_bfloat16* dl = g_vtl + (size_t)bh * HD_ * T_;
#pragma unroll
    for (int i = 0; i < 32; i += 8)
        tile[ty + i][tx] = src[(size_t)(bt + ty + i) * HD_ + bd + tx];
    __syncthreads();
#pragma unroll
    for (int i = 0; i < 32; i += 8) {
        const float v = tile[tx][ty + i];
        __nv_bfloat16 h, l;
        split1(v, h, l);
        const size_t o = (size_t)(bd + ty + i) * T_ + bt + tx;
        dh[o] = h; dl[o] = l;
    }
}

// ---------------------------------------------------------------------------
// bf16 split-GEMM with ldmatrix fragment loading.
// ---------------------------------------------------------------------------
#define PB    40
#define MATB  (128 * PB * 2)
#define BUFB  (4 * MATB)
#define BGEMM_SMEM (2 * BUFB)

template<int MODE>
__global__ __launch_bounds__(256, 2)
void bgemm(const __nv_bfloat16* __restrict__ Ah, const __nv_bfloat16* __restrict__ Al,
           const __nv_bfloat16* __restrict__ Bh, const __nv_bfloat16* __restrict__ Bl,
           float* __restrict__ Cout, int N, int K)
{
    extern __shared__ char smc[];
    const uint32_t sb = smem_u32(smc);

    const int tid  = threadIdx.x;
    const int wid  = tid >> 5;
    const int lane = tid & 31;
    const int g    = lane >> 2;
    const int tig  = lane & 3;
    const int lq   = lane >> 3;    // ldmatrix quad 0..3
    const int lr   = lane & 7;
    const int warp_m = wid >> 2;
    const int warp_n = wid & 3;
    const int bm = blockIdx.y;
    const int bn = blockIdx.x;

    const char* gsrc[4] = {
        (const char*)(Ah + (size_t)bm * 128 * K),
        (const char*)(Al + (size_t)bm * 128 * K),
        (const char*)(Bh + (size_t)bn * 128 * K),
        (const char*)(Bl + (size_t)bn * 128 * K)
    };
    const size_t grs = (size_t)K * 2;

    float acc[4][4][4];
#pragma unroll
    for (int i = 0; i < 4; i++)
#pragma unroll
        for (int j = 0; j < 4; j++)
#pragma unroll
            for (int e = 0; e < 4; e++) acc[i][j][e] = 0.0f;

    const int NT = K / 32;

#pragma unroll
    for (int p = 0; p < 8; p++) {
        const int c   = tid + p * 256;
        const int mat = c >> 9;
        const int r   = (c >> 2) & 127;
        const int q   = (c & 3) * 16;
        cp_async16(sb + mat * MATB + r * (PB * 2) + q,
                   gsrc[mat] + (size_t)r * grs + q);
    }
    cp_commit();
    cp_wait0();
    __syncthreads();

    // ldmatrix lane-address components
    const uint32_t aRow = lr + (lq & 1) * 8;        // + tile row base
    const uint32_t aCol = (lq >> 1) * 16;           // + ks*32
    const uint32_t bRow = lr + (lq >> 1) * 8;       // + pair row base
    const uint32_t bCol = (lq & 1) * 16;            // + ks*32

    for (int t = 0; t < NT; t++) {
        const int buf = t & 1;

        if (t + 1 < NT) {
            const uint32_t db = sb + (buf ^ 1) * BUFB;
            const size_t kb = (size_t)(t + 1) * 64;
#pragma unroll
            for (int p = 0; p < 8; p++) {
                const int c   = tid + p * 256;
                const int mat = c >> 9;
                const int r   = (c >> 2) & 127;
                const int q   = (c & 3) * 16;
                cp_async16(db + mat * MATB + r * (PB * 2) + q,
                           gsrc[mat] + (size_t)r * grs + kb + q);
            }
            cp_commit();
        }

        const uint32_t base = sb + buf * BUFB;
#pragma unroll
        for (int ks = 0; ks < 2; ks++) {
            const uint32_t ko = ks * 32;

            uint32_t ah[4][4], al[4][4], bh[4][2], bl[4][2];
#pragma unroll
            for (int i = 0; i < 4; i++) {
                const uint32_t ao = (warp_m * 64 + i * 16 + aRow) * (PB * 2) + ko + aCol;
                ldsm4(ah[i], base + ao);
                ldsm4(al[i], base + MATB + ao);
            }
#pragma unroll
            for (int jp = 0; jp < 2; jp++) {
                const uint32_t bo = (warp_n * 32 + jp * 16 + bRow) * (PB * 2) + ko + bCol;
                uint32_t th[4], tl[4];
                ldsm4(th, base + 2 * MATB + bo);
                bh[2*jp][0] = th[0]; bh[2*jp][1] = th[1];
                bh[2*jp+1][0] = th[2]; bh[2*jp+1][1] = th[3];
                ldsm4(tl, base + 3 * MATB + bo);
                bl[2*jp][0] = tl[0]; bl[2*jp][1] = tl[1];
                bl[2*jp+1][0] = tl[2]; bl[2*jp+1][1] = tl[3];
            }

#pragma unroll
            for (int i = 0; i < 4; i++)
#pragma unroll
                for (int j = 0; j < 4; j++)
                    mma_bf16(acc[i][j], ah[i], bh[j]);
#pragma unroll
            for (int i = 0; i < 4; i++)
#pragma unroll
                for (int j = 0; j < 4; j++)
                    mma_bf16(acc[i][j], al[i], bh[j]);
#pragma unroll
            for (int i = 0; i < 4; i++)
#pragma unroll
                for (int j = 0; j < 4; j++)
                    mma_bf16(acc[i][j], ah[i], bl[j]);
        }

        if (t + 1 < NT) cp_wait0();
        __syncthreads();
    }

#pragma unroll
    for (int i = 0; i < 4; i++) {
        const int r0 = bm * 128 + warp_m * 64 + i * 16 + g;
#pragma unroll
        for (int j = 0; j < 4; j++) {
            const int c0 = bn * 128 + warp_n * 32 + j * 8 + tig * 2;
#pragma unroll
            for (int half = 0; half < 2; half++) {
                const int r = r0 + half * 8;
                const float2 v = make_float2(acc[i][j][half * 2], acc[i][j][half * 2 + 1]);
                if (MODE == 0) {
                    const int b    = r >> 11;
                    const int tt   = r & (T_ - 1);
                    const int part = c0 >> 10;
                    const int idx  = c0 & 1023;
                    const int h    = idx >> 6;
                    const int d    = idx & 63;
                    float* dst = (part == 0) ? g_q : (part == 1) ? g_k : g_v;
                    *(float2*)(dst + (((size_t)b * H_ + h) * T_ + tt) * HD_ + d) = v;
                } else {
                    *(float2*)(Cout + (size_t)r * N + c0) = v;
                }
            }
        }
    }
}

// ---------------------------------------------------------------------------
// RoPE (unchanged from R9): fp32 q/k -> split bf16
// ---------------------------------------------------------------------------
__global__ void rope_kernel()
{
    const int idx = blockIdx.x * blockDim.x + threadIdx.x;
    const int j  = idx & 31;
    const int t  = (idx >> 5) & (T_ - 1);
    const int bh = idx >> 16;

    const float f = exp2f(-(float)j * (13.287712379549449f / 32.0f));
    float s, c;
    sincosf((float)t * f, &s, &c);

    const size_t base = ((size_t)bh * T_ + t) * HD_;
    float a0 = g_q[base + j], b0 = g_q[base + j + 32];
    float a1 = g_k[base + j], b1 = g_k[base + j + 32];
    const float q0 = a0 * c - b0 * s, q1 = b0 * c + a0 * s;
    const float k0 = a1 * c - b1 * s, k1 = b1 * c + a1 * s;
    __nv_bfloat16 h, l;
    split1(q0, h, l); g_qh[base + j] = h;      g_ql[base + j] = l;
    split1(q1, h, l); g_qh[base + j + 32] = h; g_ql[base + j + 32] = l;
    split1(k0, h, l); g_kh[base + j] = h;      g_kl[base + j] = l;
    split1(k1, h, l); g_kh[base + j + 32] = h; g_kl[base + j + 32] = l;
}

// ---------------------------------------------------------------------------
// Tensor-core flash attention with ldmatrix fragment loading.
// ---------------------------------------------------------------------------
#define KPIT 72
#define VPIT 136
#define SM_KH 0
#define SM_KL (128 * KPIT)
#define SM_VH (2 * 128 * KPIT)
#define SM_VL (2 * 128 * KPIT + 64 * VPIT)
#define FLASH_SMEM ((2 * 128 * KPIT + 2 * 64 * VPIT) * 2)

__global__ __launch_bounds__(256, 1)
void flash_tc()
{
    extern __shared__ __nv_bfloat16 smb[];
    __nv_bfloat16* Karr[2] = { smb + SM_KH, smb + SM_KL };
    __nv_bfloat16* Varr[2] = { smb + SM_VH, smb + SM_VL };
    const uint32_t skh = smem_u32(smb + SM_KH);
    const uint32_t skl = smem_u32(smb + SM_KL);
    const uint32_t svh = smem_u32(smb + SM_VH);
    const uint32_t svl = smem_u32(smb + SM_VL);

    const int tid  = threadIdx.x;
    const int wid  = tid >> 5;
    const int lane = tid & 31;
    const int g    = lane >> 2;
    const int tig  = lane & 3;
    const int lq   = lane >> 3;
    const int lr   = lane & 7;
    const int qtile = (int)gridDim.x - 1 - (int)blockIdx.x;
    const int bh    = blockIdx.y;

    const size_t qkbase = ((size_t)bh * T_ + (size_t)qtile * 128) * HD_;
    const size_t kvrow0 = (size_t)bh * T_ * HD_;
    const size_t vtbase = (size_t)bh * HD_ * T_;

    // ldmatrix lane-address components
    const uint32_t aRow = lr + (lq & 1) * 8;   // A-type (Q)
    const uint32_t aCol = (lq >> 1) * 16;
    const uint32_t bRow = lr + (lq >> 1) * 8;  // B-type (K, Vt)
    const uint32_t bCol = (lq & 1) * 16;

    // ---- stage Q, extract A-fragments via ldmatrix, release smem ----
    {
        const __nv_bfloat16* qsrc[2] = { g_qh + qkbase, g_ql + qkbase };
#pragma unroll
        for (int p = 0; p < 8; p++) {
            const int c   = tid + p * 256;
            const int mat = c >> 10;
            const int rem = c & 1023;
            const int r   = rem >> 3;
            const int c8  = (rem & 7) * 8;
            *(uint4*)(Karr[mat] + r * KPIT + c8) =
                *(const uint4*)(qsrc[mat] + r * HD_ + c8);
        }
    }
    __syncthreads();

    uint32_t qfh[4][4], qfl[4][4];
#pragma unroll
    for (int kb = 0; kb < 4; kb++) {
        const uint32_t qo = (16 * wid + aRow) * (KPIT * 2) + kb * 32 + aCol;
        ldsm4(qfh[kb], skh + qo);
        ldsm4(qfl[kb], skl + qo);
    }

    float o[8][4];
#pragma unroll
    for (int nt = 0; nt < 8; nt++)
#pragma unroll
        for (int e = 0; e < 4; e++) o[nt][e] = 0.0f;
    float m0 = -INFINITY, m1 = -INFINITY, l0 = 0.0f, l1 = 0.0f;

    for (int kv = 0; kv <= qtile; kv++) {
        __syncthreads();
        {
            const __nv_bfloat16* ksrc[2] = { g_kh + kvrow0 + (size_t)kv * 128 * HD_,
                                             g_kl + kvrow0 + (size_t)kv * 128 * HD_ };
            const __nv_bfloat16* vsrc[2] = { g_vth + vtbase + (size_t)kv * 128,
                                             g_vtl + vtbase + (size_t)kv * 128 };
#pragma unroll
            for (int p = 0; p < 8; p++) {
                const int c   = tid + p * 256;
                const int mat = c >> 10;
                const int rem = c & 1023;
                const int r   = rem >> 3;
                const int c8  = (rem & 7) * 8;
                *(uint4*)(Karr[mat] + r * KPIT + c8) =
                    *(const uint4*)(ksrc[mat] + r * HD_ + c8);
            }
#pragma unroll
            for (int p = 0; p < 8; p++) {
                const int c   = tid + p * 256;
                const int mat = c >> 10;
                const int rem = c & 1023;
                const int d   = rem >> 4;
                const int c8  = (rem & 15) * 8;
                *(uint4*)(Varr[mat] + d * VPIT + c8) =
                    *(const uint4*)(vsrc[mat] + (size_t)d * T_ + c8);
            }
        }
        __syncthreads();

        // ---- S = Q K^T (split 3-mma, ldmatrix K frags: 2 tiles per LDSM) ----
        float cS[16][4];
#pragma unroll
        for (int j = 0; j < 16; j++)
#pragma unroll
            for (int e = 0; e < 4; e++) cS[j][e] = 0.0f;

#pragma unroll
        for (int kb = 0; kb < 4; kb++) {
#pragma unroll
            for (int jp = 0; jp < 8; jp++) {
                const uint32_t koff = (jp * 16 + bRow) * (KPIT * 2) + kb * 32 + bCol;
                uint32_t th[4], tl[4];
                ldsm4(th, skh + koff);
                mma_bf16(cS[2*jp],   qfh[kb], th);
                mma_bf16(cS[2*jp],   qfl[kb], th);
                mma_bf16(cS[2*jp+1], qfh[kb], th + 2);
                mma_bf16(cS[2*jp+1], qfl[kb], th + 2);
                ldsm4(tl, skl + koff);
                mma_bf16(cS[2*jp],   qfh[kb], tl);
                mma_bf16(cS[2*jp+1], qfh[kb], tl + 2);
            }
        }

        // ---- scale + causal mask ----
        const bool diag = (kv == qtile);
        const int row0 = 16 * wid + g;
#pragma unroll
        for (int j = 0; j < 16; j++) {
            const int col0 = j * 8 + 2 * tig;
            cS[j][0] *= 0.125f; cS[j][1] *= 0.125f;
            cS[j][2] *= 0.125f; cS[j][3] *= 0.125f;
            if (diag) {
                if (col0     > row0)     cS[j][0] = -1e30f;
                if (col0 + 1 > row0)     cS[j][1] = -1e30f;
                if (col0     > row0 + 8) cS[j][2] = -1e30f;
                if (col0 + 1 > row0 + 8) cS[j][3] = -1e30f;
            }
        }

        // ---- online softmax ----
        float mx0 = -INFINITY, mx1 = -INFINITY;
#pragma unroll
        for (int j = 0; j < 16; j++) {
            mx0 = fmaxf(mx0, fmaxf(cS[j][0], cS[j][1]));
            mx1 = fmaxf(mx1, fmaxf(cS[j][2], cS[j][3]));
        }
        mx0 = fmaxf(mx0, __shfl_xor_sync(0xffffffffu, mx0, 1));
        mx0 = fmaxf(mx0, __shfl_xor_sync(0xffffffffu, mx0, 2));
        mx1 = fmaxf(mx1, __shfl_xor_sync(0xffffffffu, mx1, 1));
        mx1 = fmaxf(mx1, __shfl_xor_sync(0xffffffffu, mx1, 2));

        const float nm0 = fmaxf(m0, mx0), nm1 = fmaxf(m1, mx1);
        const float al0 = __expf(m0 - nm0), al1 = __expf(m1 - nm1);
        m0 = nm0; m1 = nm1;

        float rs0 = 0.0f, rs1 = 0.0f;
#pragma unroll
        for (int j = 0; j < 16; j++) {
            cS[j][0] = __expf(cS[j][0] - m0);
            cS[j][1] = __expf(cS[j][1] - m0);
            cS[j][2] = __expf(cS[j][2] - m1);
            cS[j][3] = __expf(cS[j][3] - m1);
            rs0 += cS[j][0] + cS[j][1];
            rs1 += cS[j][2] + cS[j][3];
        }
        rs0 += __shfl_xor_sync(0xffffffffu, rs0, 1);
        rs0 += __shfl_xor_sync(0xffffffffu, rs0, 2);
        rs1 += __shfl_xor_sync(0xffffffffu, rs1, 1);
        rs1 += __shfl_xor_sync(0xffffffffu, rs1, 2);
        l0 = l0 * al0 + rs0;
        l1 = l1 * al1 + rs1;

#pragma unroll
        for (int nt = 0; nt < 8; nt++) {
            o[nt][0] *= al0; o[nt][1] *= al0;
            o[nt][2] *= al1; o[nt][3] *= al1;
        }

        // ---- PV (ldmatrix V frags: 2 tiles per LDSM) ----
#pragma unroll
        for (int kb2 = 0; kb2 < 8; kb2++) {
            uint32_t aph[4], apl[4];
            split2(cS[2*kb2][0],   cS[2*kb2][1],   aph[0], apl[0]);
            split2(cS[2*kb2][2],   cS[2*kb2][3],   aph[1], apl[1]);
            split2(cS[2*kb2+1][0], cS[2*kb2+1][1], aph[2], apl[2]);
            split2(cS[2*kb2+1][2], cS[2*kb2+1][3], aph[3], apl[3]);
#pragma unroll
            for (int np = 0; np < 4; np++) {
                const uint32_t voff = (np * 16 + bRow) * (VPIT * 2) + kb2 * 32 + bCol;
                uint32_t th[4], tl[4];
                ldsm4(th, svh + voff);
                mma_bf16(o[2*np],   aph, th);
                mma_bf16(o[2*np],   apl, th);
                mma_bf16(o[2*np+1], aph, th + 2);
                mma_bf16(o[2*np+1], apl, th + 2);
                ldsm4(tl, svl + voff);
                mma_bf16(o[2*np],   aph, tl);
                mma_bf16(o[2*np+1], aph, tl + 2);
            }
        }
    }

    // ---- epilogue ----
    const int b = bh >> 4;
    const int h = bh & 15;
    const int t0 = qtile * 128 + 16 * wid + g;
    const float inv0 = 1.0f / l0, inv1 = 1.0f / l1;
#pragma unroll
    for (int nt = 0; nt < 8; nt++) {
        const int d = nt * 8 + 2 * tig;
        uint32_t ph, pl;
        split2(o[nt][0] * inv0, o[nt][1] * inv0, ph, pl);
        const size_t off0 = ((size_t)b * T_ + t0) * D_ + h * HD_ + d;
        *(uint32_t*)(g_atth + off0) = ph;
        *(uint32_t*)(g_attl + off0) = pl;
        split2(o[nt][2] * inv1, o[nt][3] * inv1, ph, pl);
        const size_t off1 = ((size_t)b * T_ + t0 + 8) * D_ + h * HD_ + d;
        *(uint32_t*)(g_atth + off1) = ph;
        *(uint32_t*)(g_attl + off1) = pl;
    }
}

// ---------------------------------------------------------------------------
extern "C" void kernel_launch(void* const* d_in, const int* in_sizes, int n_in,
                              void* d_out, int out_size)
{
    const float* x     = (const float*)d_in[0];
    // d_in[1] = mask (causal, static — ignored)
    const float* w_qkv = (const float*)d_in[2];
    const float* w_out = (const float*)d_in[3];
    float* out = (float*)d_out;

    cudaFuncSetAttribute(bgemm<0>, cudaFuncAttributeMaxDynamicSharedMemorySize, BGEMM_SMEM);
    cudaFuncSetAttribute(bgemm<1>, cudaFuncAttributeMaxDynamicSharedMemorySize, BGEMM_SMEM);
    cudaFuncSetAttribute(flash_tc, cudaFuncAttributeMaxDynamicSharedMemorySize, FLASH_SMEM);

    __nv_bfloat16 *xh, *xl, *wqh, *wql, *woh, *wol, *ath, *atl;
    cudaGetSymbolAddress((void**)&xh,  g_xh);     cudaGetSymbolAddress((void**)&xl,  g_xl);
    cudaGetSymbolAddress((void**)&wqh, g_wqkvTh); cudaGetSymbolAddress((void**)&wql, g_wqkvTl);
    cudaGetSymbolAddress((void**)&woh, g_woutTh); cudaGetSymbolAddress((void**)&wol, g_woutTl);
    cudaGetSymbolAddress((void**)&ath, g_atth);   cudaGetSymbolAddress((void**)&atl, g_attl);

    // 0) split x; split+transpose weights
    split4_kernel<<<(M_*D_/4 + 255)/256, 256>>>((const float4*)x,
        (__nv_bfloat162*)xh, (__nv_bfloat162*)xl, M_*D_/4);
    splitT_kernel<<<dim3(NQKV_/32, D_/32), dim3(32, 8)>>>(w_qkv, wqh, wql, D_, NQKV_);
    splitT_kernel<<<dim3(D_/32,  D_/32), dim3(32, 8)>>>(w_out, woh, wol, D_, D_);

    // 1) qkv = x @ w_qkv (tensor)
    bgemm<0><<<dim3(NQKV_/128, M_/128), 256, BGEMM_SMEM>>>(xh, xl, wqh, wql,
                                                           nullptr, NQKV_, K_);
    // 2) RoPE -> split bf16 q/k;  V -> transpose+split
    rope_kernel<<<(B_ * H_ * T_ * 32) / 256, 256>>>();
    vsplitT_kernel<<<dim3(T_/32, HD_/32, B_*H_), dim3(32, 8)>>>();

    // 3) tensor-core causal flash attention
    flash_tc<<<dim3(T_ / 128, B_ * H_), 256, FLASH_SMEM>>>();

    // 4) out = att @ w_out (tensor)
    bgemm<1><<<dim3(D_/128, M_/128), 256, BGEMM_SMEM>>>(ath, atl, woh, wol,
                                                        out, D_, K_);
}